// round 2
// baseline (speedup 1.0000x reference)
#include <cuda_runtime.h>
#include <math.h>

#define BB 64
#define LL 2048
#define TT 1024
#define DD 128
#define EE 512
#define HH 8
#define PP 3
#define HP 24
#define LAT 256
#define HID 512
#define NSIN 64
#define SPL 8
#define LSP (LL/SPL)

// ---------------- static device scratch (no allocations) ----------------
__device__ float g_q[PP*EE];
__device__ float g_A[EE*HP];
__device__ float g_lin[HP];
__device__ float g_off[HP];
__device__ float g_ws[NSIN];
__device__ float g_bs[NSIN];
__device__ float g_Asin[NSIN*HP];
__device__ float g_bconst[LAT];
__device__ float g_scores[BB*LL*HP];
__device__ unsigned int g_maxu[BB*HP];
__device__ float g_part[SPL*BB*HP*256];
__device__ float g_sum[BB*HP*256];
__device__ float g_Dm[BB*3*HID];
__device__ float g_H2[(size_t)BB*TT*HID];

__device__ __forceinline__ unsigned int enc_f(float f) {
    unsigned int u = __float_as_uint(f);
    return (u & 0x80000000u) ? ~u : (u | 0x80000000u);
}
__device__ __forceinline__ float dec_f(unsigned int u) {
    return (u & 0x80000000u) ? __uint_as_float(u & 0x7FFFFFFFu)
                             : __uint_as_float(~u);
}

// ---------------- K1: setup (q, A, lin/off, Asin, bconst, reset max) -----
__global__ void k_setup(const float* __restrict__ query,
                        const float* __restrict__ W_q,
                        const float* __restrict__ b_q,
                        const float* __restrict__ W_k,
                        const float* __restrict__ b_k,
                        const float* __restrict__ w_te,
                        const float* __restrict__ b_te,
                        const float* __restrict__ W_o,
                        const float* __restrict__ b_o) {
    int tid = threadIdx.x;  // 256 threads, 1 block
    for (int i = tid; i < BB*HP; i += 256) g_maxu[i] = 0u;

    // q[p,e] = query[p]@W_q + b_q
    for (int idx = tid; idx < PP*EE; idx += 256) {
        int p = idx / EE, e = idx % EE;
        float acc = b_q[e];
        for (int i = 0; i < EE; i++)
            acc = fmaf(query[p*EE + i], W_q[i*EE + e], acc);
        g_q[idx] = acc;
    }
    __syncthreads();

    // A[e,hp] = (1/8) * sum_j W_k[e, h*64+j] * q[p, h*64+j]
    for (int idx = tid; idx < EE*HP; idx += 256) {
        int e = idx / HP, hp = idx % HP;
        int h = hp / PP, p = hp % PP;
        float acc = 0.f;
        #pragma unroll 4
        for (int j = 0; j < 64; j++)
            acc = fmaf(W_k[e*EE + h*64 + j], g_q[p*EE + h*64 + j], acc);
        g_A[idx] = acc * 0.125f;
    }
    __syncthreads();

    // lin/off per hp (24 threads)
    if (tid < HP) {
        int hp = tid, h = hp / PP, p = hp % PP;
        float lin = 0.f, off = 0.f;
        for (int j = 0; j < 64; j++)
            off = fmaf(g_q[p*EE + h*64 + j], b_k[h*64 + j], off);
        off *= 0.125f;
        for (int e = 0; e < EE; e++) {
            if ((e & 7) != 0) {
                float a = g_A[e*HP + hp];
                lin = fmaf(w_te[e], a, lin);
                off = fmaf(b_te[e], a, off);
            }
        }
        g_lin[hp] = lin; g_off[hp] = off;
    }
    if (tid < NSIN) { g_ws[tid] = w_te[8*tid]; g_bs[tid] = b_te[8*tid]; }
    for (int idx = tid; idx < NSIN*HP; idx += 256) {
        int j = idx / HP, hp = idx % HP;
        g_Asin[idx] = g_A[(8*j)*HP + hp];
    }
    // bconst[n] = b_o[n] + sum over constant (x==1) rows of W_o
    for (int n = tid; n < LAT; n += 256) {
        float acc = b_o[n];
        for (int h = 0; h < HH; h++)
            for (int c = 0; c < DD; c++)
                acc += W_o[(h*256 + 128 + c)*LAT + n];
        g_bconst[n] = acc;
    }
}

// ---------------- K2: scores + per-(b,hp) max --------------------------
__global__ void k_scores(const float* __restrict__ timesteps) {
    __shared__ float s_Asin[NSIN*HP];
    __shared__ float s_lin[HP], s_off[HP];
    __shared__ float s_ws[NSIN], s_bs[NSIN];
    __shared__ unsigned int s_max[HP];
    int tid = threadIdx.x;
    int g = blockIdx.x * 256 + tid;      // b*L + l; block spans one b
    int b = g / LL;
    for (int i = tid; i < NSIN*HP; i += 256) s_Asin[i] = g_Asin[i];
    if (tid < HP) { s_lin[tid] = g_lin[tid]; s_off[tid] = g_off[tid]; s_max[tid] = 0u; }
    if (tid < NSIN) { s_ws[tid] = g_ws[tid]; s_bs[tid] = g_bs[tid]; }
    __syncthreads();

    float t = timesteps[g];
    float acc[HP];
    #pragma unroll
    for (int hp = 0; hp < HP; hp++) acc[hp] = fmaf(t, s_lin[hp], s_off[hp]);
    for (int j = 0; j < NSIN; j++) {
        float s = sinf(fmaf(t, s_ws[j], s_bs[j]));
        #pragma unroll
        for (int hp = 0; hp < HP; hp++)
            acc[hp] = fmaf(s, s_Asin[j*HP + hp], acc[hp]);
    }
    #pragma unroll
    for (int hp = 0; hp < HP; hp++) {
        g_scores[g*HP + hp] = acc[hp];
        atomicMax(&s_max[hp], enc_f(acc[hp]));
    }
    __syncthreads();
    if (tid < HP) atomicMax(&g_maxu[b*HP + tid], s_max[tid]);
}

// ---------------- K3: attention partial sums (deterministic splits) -----
__global__ void k_att_partial(const float* __restrict__ X,
                              const float* __restrict__ M) {
    __shared__ float s_m[HP];
    __shared__ float s_w[64*HP];
    int tid = threadIdx.x;               // = channel c (0..255)
    int b  = blockIdx.x / SPL;
    int sp = blockIdx.x % SPL;
    int l0 = sp * LSP;
    if (tid < HP) s_m[tid] = dec_f(g_maxu[b*HP + tid]);
    float acc[HP];
    #pragma unroll
    for (int hp = 0; hp < HP; hp++) acc[hp] = 0.f;
    int c = tid;

    for (int ch = 0; ch < LSP; ch += 64) {
        __syncthreads();
        for (int i = tid; i < 64*HP; i += 256) {
            int li = i / HP, hp = i % HP;
            float sc = g_scores[(b*LL + l0 + ch + li)*HP + hp];
            s_w[i] = expf(sc - s_m[hp]);
        }
        __syncthreads();
        for (int li = 0; li < 64; li++) {
            int l = l0 + ch + li;
            float f;
            if (c < DD) {
                float xv = X[((long)b*LL + l)*DD + c];
                float mv = M[((long)b*LL + l)*DD + c];
                f = xv * mv;
            } else {
                f = M[((long)b*LL + l)*DD + (c - DD)];
            }
            #pragma unroll
            for (int hp = 0; hp < HP; hp++)
                acc[hp] = fmaf(s_w[li*HP + hp], f, acc[hp]);
        }
    }
    for (int hp = 0; hp < HP; hp++)
        g_part[(((sp*BB) + b)*HP + hp)*256 + c] = acc[hp];
}

// ---------------- K4: fixed-order reduce over splits --------------------
__global__ void k_att_reduce() {
    int e = blockIdx.x * 256 + threadIdx.x;   // < BB*HP*256
    float acc = 0.f;
    #pragma unroll
    for (int s = 0; s < SPL; s++) acc += g_part[s*(BB*HP*256) + e];
    g_sum[e] = acc;
}

// ---------------- K5: x1, coeffs, D-matrices (per batch) ----------------
__global__ void k_coeffs(const float* __restrict__ W_o,
                         const float* __restrict__ W1,
                         const float* __restrict__ b1) {
    __shared__ float s_x1[HP*DD];     // [hp][c]
    __shared__ float s_cf[PP*LAT];    // [p][n]
    int tid = threadIdx.x;
    int b = blockIdx.x;
    for (int i = tid; i < HP*DD; i += 256) {
        int hp = i / DD, c = i % DD;
        float num = g_sum[(b*HP + hp)*256 + c];
        float den = g_sum[(b*HP + hp)*256 + 128 + c];
        s_x1[i] = num / den;
    }
    __syncthreads();
    {
        int n = tid;
        float a0 = g_bconst[n], a1 = a0, a2 = a0;
        for (int h = 0; h < HH; h++) {
            #pragma unroll 4
            for (int c = 0; c < DD; c++) {
                float wv = W_o[(h*256 + c)*LAT + n];
                a0 = fmaf(s_x1[(h*PP + 0)*DD + c], wv, a0);
                a1 = fmaf(s_x1[(h*PP + 1)*DD + c], wv, a1);
                a2 = fmaf(s_x1[(h*PP + 2)*DD + c], wv, a2);
            }
        }
        s_cf[0*LAT + n] = a0; s_cf[1*LAT + n] = a1; s_cf[2*LAT + n] = a2;
    }
    __syncthreads();
    for (int idx = tid; idx < 3*HID; idx += 256) {
        int k = idx / HID, j = idx % HID;
        float acc = (k == 0) ? b1[j] : 0.f;
        #pragma unroll 4
        for (int n = 0; n < LAT; n++)
            acc = fmaf(s_cf[k*LAT + n], W1[n*HID + j], acc);
        g_Dm[(b*3 + k)*HID + j] = acc;
    }
}

// ---------------- K6: fused h1-gen + W2 GEMM (H2 = relu(h1@W2+b2)) ------
__global__ __launch_bounds__(256, 2)
void k_mlp2(const float* __restrict__ yts,
            const float* __restrict__ W2,
            const float* __restrict__ b2) {
    __shared__ float s_t[128];
    __shared__ float s_D[3*HID];
    __shared__ float As[16][128];
    __shared__ float Bs[16][128];
    int tid = threadIdx.x;
    int b = blockIdx.x >> 3;
    int row0 = (blockIdx.x & 7) * 128;
    int n0 = blockIdx.y * 128;
    if (tid < 128) s_t[tid] = yts[b*TT + row0 + tid];
    for (int i = tid; i < 3*HID; i += 256) s_D[i] = g_Dm[b*3*HID + i];
    int tr = tid >> 4, tc = tid & 15;
    float acc[8][8];
    #pragma unroll
    for (int i = 0; i < 8; i++)
        #pragma unroll
        for (int j = 0; j < 8; j++) acc[i][j] = 0.f;

    for (int k0 = 0; k0 < HID; k0 += 16) {
        __syncthreads();
        #pragma unroll
        for (int r = 0; r < 8; r++) {            // generate h1 tile
            int idx = tid + r*256;
            int k = idx >> 7, row = idx & 127;
            float t = s_t[row];
            float d0 = s_D[k0 + k], d1 = s_D[HID + k0 + k], d2 = s_D[2*HID + k0 + k];
            As[k][row] = fmaxf(fmaf(t, fmaf(t, d2, d1), d0), 0.f);
        }
        #pragma unroll
        for (int r = 0; r < 8; r++) {            // W2 tile
            int idx = tid + r*256;
            int k = idx >> 7, n = idx & 127;
            Bs[k][n] = W2[(k0 + k)*HID + n0 + n];
        }
        __syncthreads();
        #pragma unroll
        for (int k = 0; k < 16; k++) {
            const float4* A4 = reinterpret_cast<const float4*>(&As[k][0]);
            const float4* B4 = reinterpret_cast<const float4*>(&Bs[k][0]);
            float4 a0 = A4[tr], a1 = A4[16 + tr];
            float4 b0 = B4[tc], b1v = B4[16 + tc];
            float av[8] = {a0.x,a0.y,a0.z,a0.w,a1.x,a1.y,a1.z,a1.w};
            float bv[8] = {b0.x,b0.y,b0.z,b0.w,b1v.x,b1v.y,b1v.z,b1v.w};
            #pragma unroll
            for (int i = 0; i < 8; i++)
                #pragma unroll
                for (int j = 0; j < 8; j++)
                    acc[i][j] = fmaf(av[i], bv[j], acc[i][j]);
        }
    }
    float4 bb0 = *reinterpret_cast<const float4*>(&b2[n0 + tc*4]);
    float4 bb1 = *reinterpret_cast<const float4*>(&b2[n0 + 64 + tc*4]);
    float bva[8] = {bb0.x,bb0.y,bb0.z,bb0.w,bb1.x,bb1.y,bb1.z,bb1.w};
    size_t rbase = (size_t)b*TT + row0;
    #pragma unroll
    for (int i = 0; i < 8; i++) {
        int row = (i < 4) ? (tr*4 + i) : (64 + tr*4 + i - 4);
        float4 o0, o1;
        o0.x = fmaxf(acc[i][0] + bva[0], 0.f);
        o0.y = fmaxf(acc[i][1] + bva[1], 0.f);
        o0.z = fmaxf(acc[i][2] + bva[2], 0.f);
        o0.w = fmaxf(acc[i][3] + bva[3], 0.f);
        o1.x = fmaxf(acc[i][4] + bva[4], 0.f);
        o1.y = fmaxf(acc[i][5] + bva[5], 0.f);
        o1.z = fmaxf(acc[i][6] + bva[6], 0.f);
        o1.w = fmaxf(acc[i][7] + bva[7], 0.f);
        *reinterpret_cast<float4*>(&g_H2[(rbase + row)*HID + n0 + tc*4]) = o0;
        *reinterpret_cast<float4*>(&g_H2[(rbase + row)*HID + n0 + 64 + tc*4]) = o1;
    }
}

// ---------------- K7: W3 GEMM (out = H2@W3 + b3) ------------------------
__global__ __launch_bounds__(256, 2)
void k_mlp3(const float* __restrict__ W3,
            const float* __restrict__ b3,
            float* __restrict__ out) {
    __shared__ float As[16][128];
    __shared__ float Bs[16][128];
    int tid = threadIdx.x;
    size_t r0 = (size_t)blockIdx.x * 128;
    int tr = tid >> 4, tc = tid & 15;
    float acc[8][8];
    #pragma unroll
    for (int i = 0; i < 8; i++)
        #pragma unroll
        for (int j = 0; j < 8; j++) acc[i][j] = 0.f;

    for (int k0 = 0; k0 < HID; k0 += 16) {
        __syncthreads();
        #pragma unroll
        for (int r = 0; r < 2; r++) {            // A tile from g_H2 (float4)
            int idx = tid + r*256;
            int row = idx >> 2;
            int kq = (idx & 3) * 4;
            float4 v = *reinterpret_cast<const float4*>(&g_H2[(r0 + row)*HID + k0 + kq]);
            As[kq + 0][row] = v.x; As[kq + 1][row] = v.y;
            As[kq + 2][row] = v.z; As[kq + 3][row] = v.w;
        }
        #pragma unroll
        for (int r = 0; r < 8; r++) {            // W3 tile
            int idx = tid + r*256;
            int k = idx >> 7, n = idx & 127;
            Bs[k][n] = W3[(k0 + k)*DD + n];
        }
        __syncthreads();
        #pragma unroll
        for (int k = 0; k < 16; k++) {
            const float4* A4 = reinterpret_cast<const float4*>(&As[k][0]);
            const float4* B4 = reinterpret_cast<const float4*>(&Bs[k][0]);
            float4 a0 = A4[tr], a1 = A4[16 + tr];
            float4 b0 = B4[tc], b1v = B4[16 + tc];
            float av[8] = {a0.x,a0.y,a0.z,a0.w,a1.x,a1.y,a1.z,a1.w};
            float bv[8] = {b0.x,b0.y,b0.z,b0.w,b1v.x,b1v.y,b1v.z,b1v.w};
            #pragma unroll
            for (int i = 0; i < 8; i++)
                #pragma unroll
                for (int j = 0; j < 8; j++)
                    acc[i][j] = fmaf(av[i], bv[j], acc[i][j]);
        }
    }
    float4 bb0 = *reinterpret_cast<const float4*>(&b3[tc*4]);
    float4 bb1 = *reinterpret_cast<const float4*>(&b3[64 + tc*4]);
    float bva[8] = {bb0.x,bb0.y,bb0.z,bb0.w,bb1.x,bb1.y,bb1.z,bb1.w};
    #pragma unroll
    for (int i = 0; i < 8; i++) {
        int row = (i < 4) ? (tr*4 + i) : (64 + tr*4 + i - 4);
        float4 o0, o1;
        o0.x = acc[i][0] + bva[0]; o0.y = acc[i][1] + bva[1];
        o0.z = acc[i][2] + bva[2]; o0.w = acc[i][3] + bva[3];
        o1.x = acc[i][4] + bva[4]; o1.y = acc[i][5] + bva[5];
        o1.z = acc[i][6] + bva[6]; o1.w = acc[i][7] + bva[7];
        *reinterpret_cast<float4*>(&out[(r0 + row)*DD + tc*4]) = o0;
        *reinterpret_cast<float4*>(&out[(r0 + row)*DD + 64 + tc*4]) = o1;
    }
}

// ---------------- launch -------------------------------------------------
extern "C" void kernel_launch(void* const* d_in, const int* in_sizes, int n_in,
                              void* d_out, int out_size) {
    const float* timesteps = (const float*)d_in[0];
    const float* X         = (const float*)d_in[1];
    const float* M         = (const float*)d_in[2];
    const float* yts       = (const float*)d_in[3];
    const float* w_te      = (const float*)d_in[4];
    const float* b_te      = (const float*)d_in[5];
    const float* query     = (const float*)d_in[6];
    const float* W_q       = (const float*)d_in[7];
    const float* b_q       = (const float*)d_in[8];
    const float* W_k       = (const float*)d_in[9];
    const float* b_k       = (const float*)d_in[10];
    const float* W_o       = (const float*)d_in[11];
    const float* b_o       = (const float*)d_in[12];
    const float* W1        = (const float*)d_in[13];
    const float* b1        = (const float*)d_in[14];
    const float* W2        = (const float*)d_in[15];
    const float* b2        = (const float*)d_in[16];
    const float* W3        = (const float*)d_in[17];
    const float* b3        = (const float*)d_in[18];
    float* out = (float*)d_out;

    k_setup<<<1, 256>>>(query, W_q, b_q, W_k, b_k, w_te, b_te, W_o, b_o);
    k_scores<<<BB*LL/256, 256>>>(timesteps);
    k_att_partial<<<SPL*BB, 256>>>(X, M);
    k_att_reduce<<<BB*HP, 256>>>();
    k_coeffs<<<BB, 256>>>(W_o, W1, b1);
    k_mlp2<<<dim3(BB*TT/128, 4), 256>>>(yts, W2, b2);
    k_mlp3<<<BB*TT/128, 256>>>(W3, b3, out);
}

// round 5
// speedup vs baseline: 1.9641x; 1.9641x over previous
#include <cuda_runtime.h>
#include <cuda_bf16.h>
#include <math.h>
#include <stdint.h>

#define BB 64
#define LL 2048
#define TT 1024
#define DD 128
#define EE 512
#define HH 8
#define PP 3
#define HP 24
#define LAT 256
#define HID 512
#define NSIN 64
#define SPL 8
#define LSP (LL/SPL)
#define KP 1536          // tripled K for split GEMM
#define NKC 48           // K' chunks of 32
#define AROW 40          // padded smem row (bf16 elems) = 80 bytes

// ---------------- static device scratch (no allocations) ----------------
__device__ float g_q[PP*EE];
__device__ float g_A[EE*HP];
__device__ float g_lin[HP];
__device__ float g_off[HP];
__device__ float g_ws[NSIN];
__device__ float g_bs[NSIN];
__device__ float g_Asin[NSIN*HP];
__device__ float g_bconst[LAT];
__device__ float g_scores[BB*LL*HP];
__device__ unsigned int g_maxu[BB*HP];
__device__ float g_part[SPL*BB*HP*256];
__device__ float g_sum[BB*HP*256];
__device__ float g_Dm[BB*3*HID];
__device__ __align__(16) __nv_bfloat16 g_B2[512*KP];         // W2' split, [n][k']
__device__ __align__(16) __nv_bfloat16 g_B3[128*KP];         // W3' split, [n][k']
__device__ __align__(16) __nv_bfloat16 g_H2h[(size_t)BB*TT*HID];
__device__ __align__(16) __nv_bfloat16 g_H2l[(size_t)BB*TT*HID];

__device__ __forceinline__ unsigned int enc_f(float f) {
    unsigned int u = __float_as_uint(f);
    return (u & 0x80000000u) ? ~u : (u | 0x80000000u);
}
__device__ __forceinline__ float dec_f(unsigned int u) {
    return (u & 0x80000000u) ? __uint_as_float(u & 0x7FFFFFFFu)
                             : __uint_as_float(~u);
}

// ---------------- PTX helpers -------------------------------------------
__device__ __forceinline__ uint32_t smem_u32(const void* p) {
    uint32_t a;
    asm("{ .reg .u64 t; cvta.to.shared.u64 t, %1; cvt.u32.u64 %0, t; }"
        : "=r"(a) : "l"(p));
    return a;
}
__device__ __forceinline__ uint32_t pack2(float a, float b) {
    __nv_bfloat162 h = __floats2bfloat162_rn(a, b);
    return *reinterpret_cast<uint32_t*>(&h);
}

#define CP16(dst, src) \
    asm volatile("cp.async.cg.shared.global [%0], [%1], 16;" :: "r"(dst), "l"(src))
#define CP_COMMIT() asm volatile("cp.async.commit_group;" ::: "memory")
#define CP_WAIT(n)  asm volatile("cp.async.wait_group %0;" :: "n"(n) : "memory")

#define LDM_X4(r, addr) \
    asm volatile("ldmatrix.sync.aligned.m8n8.x4.shared.b16 {%0,%1,%2,%3}, [%4];" \
        : "=r"((r)[0]), "=r"((r)[1]), "=r"((r)[2]), "=r"((r)[3]) : "r"(addr))

#define MMA16816(c, a, b0, b1) \
    asm volatile("mma.sync.aligned.m16n8k16.row.col.f32.bf16.bf16.f32 " \
        "{%0,%1,%2,%3}, {%4,%5,%6,%7}, {%8,%9}, {%0,%1,%2,%3};" \
        : "+f"((c)[0]), "+f"((c)[1]), "+f"((c)[2]), "+f"((c)[3]) \
        : "r"((a)[0]), "r"((a)[1]), "r"((a)[2]), "r"((a)[3]), "r"(b0), "r"(b1))

// ---------------- setup kernels -----------------------------------------
__global__ void k_setup_q(const float* __restrict__ query,
                          const float* __restrict__ W_q,
                          const float* __restrict__ b_q) {
    int idx = blockIdx.x * 256 + threadIdx.x;   // < 1536
    int p = idx / EE, e = idx % EE;
    float acc = b_q[e];
    for (int i = 0; i < EE; i++)
        acc = fmaf(query[p*EE + i], W_q[i*EE + e], acc);
    g_q[idx] = acc;
}

__global__ void k_setup_A(const float* __restrict__ W_k) {
    int idx = blockIdx.x * 256 + threadIdx.x;   // < 12288
    int e = idx / HP, hp = idx % HP;
    int h = hp / PP, p = hp % PP;
    float acc = 0.f;
    #pragma unroll 4
    for (int j = 0; j < 64; j++)
        acc = fmaf(W_k[e*EE + h*64 + j], g_q[p*EE + h*64 + j], acc);
    g_A[idx] = acc * 0.125f;
}

__global__ void k_setup_misc(const float* __restrict__ b_k,
                             const float* __restrict__ w_te,
                             const float* __restrict__ b_te,
                             const float* __restrict__ W_o,
                             const float* __restrict__ b_o) {
    int tid = threadIdx.x;
    int bid = blockIdx.x;
    if (bid == 0) {
        if (tid < HP) {
            int hp = tid, h = hp / PP, p = hp % PP;
            float lin = 0.f, off = 0.f;
            for (int j = 0; j < 64; j++)
                off = fmaf(g_q[p*EE + h*64 + j], b_k[h*64 + j], off);
            off *= 0.125f;
            for (int e = 0; e < EE; e++) {
                if ((e & 7) != 0) {
                    float a = g_A[e*HP + hp];
                    lin = fmaf(w_te[e], a, lin);
                    off = fmaf(b_te[e], a, off);
                }
            }
            g_lin[hp] = lin; g_off[hp] = off;
        }
        if (tid < NSIN) { g_ws[tid] = w_te[8*tid]; g_bs[tid] = b_te[8*tid]; }
    } else if (bid == 1) {
        for (int idx = tid; idx < NSIN*HP; idx += 256) {
            int j = idx / HP, hp = idx % HP;
            g_Asin[idx] = g_A[(8*j)*HP + hp];
        }
        for (int i = tid; i < BB*HP; i += 256) g_maxu[i] = 0u;
    } else {
        int n = (bid - 2) * 128 + (tid & 127);
        int half = tid >> 7;
        float acc = (half == 0) ? b_o[n] : 0.f;
        for (int h = half*4; h < half*4 + 4; h++)
            for (int c = 0; c < DD; c++)
                acc += W_o[(h*256 + 128 + c)*LAT + n];
        __shared__ float s_p[128];
        if (half == 1) s_p[tid & 127] = acc;
        __syncthreads();
        if (half == 0) g_bconst[n] = acc + s_p[tid];
    }
}

// ---------------- W2'/W3' split prep ------------------------------------
__global__ void k_prepW(const float* __restrict__ W2,
                        const float* __restrict__ W3) {
    int i0 = blockIdx.x * 256 + threadIdx.x;
    int stride = gridDim.x * 256;
    for (int idx = i0; idx < 512*512; idx += stride) {
        int k = idx >> 9, n = idx & 511;
        float w = W2[idx];
        __nv_bfloat16 h = __float2bfloat16_rn(w);
        __nv_bfloat16 l = __float2bfloat16_rn(w - __bfloat162float(h));
        g_B2[n*KP + k] = h;
        g_B2[n*KP + 512 + k] = h;
        g_B2[n*KP + 1024 + k] = l;
    }
    for (int idx = i0; idx < 512*128; idx += stride) {
        int k = idx >> 7, n = idx & 127;
        float w = W3[idx];
        __nv_bfloat16 h = __float2bfloat16_rn(w);
        __nv_bfloat16 l = __float2bfloat16_rn(w - __bfloat162float(h));
        g_B3[n*KP + k] = h;
        g_B3[n*KP + 512 + k] = h;
        g_B3[n*KP + 1024 + k] = l;
    }
}

// ---------------- K2: scores + per-(b,hp) max ---------------------------
__global__ void k_scores(const float* __restrict__ timesteps) {
    __shared__ float s_Asin[NSIN*HP];
    __shared__ float s_lin[HP], s_off[HP];
    __shared__ float s_ws[NSIN], s_bs[NSIN];
    __shared__ unsigned int s_max[HP];
    int tid = threadIdx.x;
    int g = blockIdx.x * 256 + tid;
    int b = g / LL;
    for (int i = tid; i < NSIN*HP; i += 256) s_Asin[i] = g_Asin[i];
    if (tid < HP) { s_lin[tid] = g_lin[tid]; s_off[tid] = g_off[tid]; s_max[tid] = 0u; }
    if (tid < NSIN) { s_ws[tid] = g_ws[tid]; s_bs[tid] = g_bs[tid]; }
    __syncthreads();

    float t = timesteps[g];
    float acc[HP];
    #pragma unroll
    for (int hp = 0; hp < HP; hp++) acc[hp] = fmaf(t, s_lin[hp], s_off[hp]);
    for (int j = 0; j < NSIN; j++) {
        float s = sinf(fmaf(t, s_ws[j], s_bs[j]));
        #pragma unroll
        for (int hp = 0; hp < HP; hp++)
            acc[hp] = fmaf(s, s_Asin[j*HP + hp], acc[hp]);
    }
    #pragma unroll
    for (int hp = 0; hp < HP; hp++) {
        g_scores[g*HP + hp] = acc[hp];
        atomicMax(&s_max[hp], enc_f(acc[hp]));
    }
    __syncthreads();
    if (tid < HP) atomicMax(&g_maxu[b*HP + tid], s_max[tid]);
}

// ---------------- K3: attention partial sums ----------------------------
__global__ void k_att_partial(const float* __restrict__ X,
                              const float* __restrict__ M) {
    __shared__ float s_m[HP];
    __shared__ float s_w[64*HP];
    int tid = threadIdx.x;
    int b  = blockIdx.x / SPL;
    int sp = blockIdx.x % SPL;
    int l0 = sp * LSP;
    if (tid < HP) s_m[tid] = dec_f(g_maxu[b*HP + tid]);
    float acc[HP];
    #pragma unroll
    for (int hp = 0; hp < HP; hp++) acc[hp] = 0.f;
    int c = tid;

    for (int ch = 0; ch < LSP; ch += 64) {
        __syncthreads();
        for (int i = tid; i < 64*HP; i += 256) {
            int li = i / HP, hp = i % HP;
            float sc = g_scores[(b*LL + l0 + ch + li)*HP + hp];
            s_w[i] = expf(sc - s_m[hp]);
        }
        __syncthreads();
        for (int li = 0; li < 64; li++) {
            int l = l0 + ch + li;
            float f;
            if (c < DD) {
                float xv = X[((long)b*LL + l)*DD + c];
                float mv = M[((long)b*LL + l)*DD + c];
                f = xv * mv;
            } else {
                f = M[((long)b*LL + l)*DD + (c - DD)];
            }
            #pragma unroll
            for (int hp = 0; hp < HP; hp++)
                acc[hp] = fmaf(s_w[li*HP + hp], f, acc[hp]);
        }
    }
    for (int hp = 0; hp < HP; hp++)
        g_part[(((sp*BB) + b)*HP + hp)*256 + c] = acc[hp];
}

// ---------------- K4: fixed-order reduce --------------------------------
__global__ void k_att_reduce() {
    int e = blockIdx.x * 256 + threadIdx.x;
    float acc = 0.f;
    #pragma unroll
    for (int s = 0; s < SPL; s++) acc += g_part[s*(BB*HP*256) + e];
    g_sum[e] = acc;
}

// ---------------- K5: x1, coeffs, D-matrices ----------------------------
__global__ void k_coeffs(const float* __restrict__ W_o,
                         const float* __restrict__ W1,
                         const float* __restrict__ b1) {
    __shared__ float s_x1[HP*DD];
    __shared__ float s_cf[PP*LAT];
    int tid = threadIdx.x;
    int b = blockIdx.x;
    for (int i = tid; i < HP*DD; i += 256) {
        int hp = i / DD, c = i % DD;
        float num = g_sum[(b*HP + hp)*256 + c];
        float den = g_sum[(b*HP + hp)*256 + 128 + c];
        s_x1[i] = num / den;
    }
    __syncthreads();
    {
        int n = tid;
        float a0 = g_bconst[n], a1 = a0, a2 = a0;
        for (int h = 0; h < HH; h++) {
            #pragma unroll 4
            for (int c = 0; c < DD; c++) {
                float wv = W_o[(h*256 + c)*LAT + n];
                a0 = fmaf(s_x1[(h*PP + 0)*DD + c], wv, a0);
                a1 = fmaf(s_x1[(h*PP + 1)*DD + c], wv, a1);
                a2 = fmaf(s_x1[(h*PP + 2)*DD + c], wv, a2);
            }
        }
        s_cf[0*LAT + n] = a0; s_cf[1*LAT + n] = a1; s_cf[2*LAT + n] = a2;
    }
    __syncthreads();
    for (int idx = tid; idx < 3*HID; idx += 256) {
        int k = idx / HID, j = idx % HID;
        float acc = (k == 0) ? b1[j] : 0.f;
        #pragma unroll 4
        for (int n = 0; n < LAT; n++)
            acc = fmaf(s_cf[k*LAT + n], W1[n*HID + j], acc);
        g_Dm[(b*3 + k)*HID + j] = acc;
    }
}

// ---------------- shared compute core for mma GEMMs ---------------------
__device__ __forceinline__ void mma_compute_chunk(
    float acc[2][8][4], uint32_t asb, uint32_t bsb,
    int m0w, int n0w, int lane)
{
    #pragma unroll
    for (int ks = 0; ks < 2; ks++) {
        uint32_t a[2][4];
        #pragma unroll
        for (int mi = 0; mi < 2; mi++) {
            uint32_t ad = asb + (uint32_t)(m0w + mi*16 + (lane & 15)) * 80
                        + (uint32_t)(ks*32 + ((lane >> 4) << 4));
            LDM_X4(a[mi], ad);
        }
        uint32_t bfr[4][4];
        #pragma unroll
        for (int nt = 0; nt < 4; nt++) {
            int rown = n0w + nt*16 + ((lane >> 4) << 3) + (lane & 7);
            uint32_t bd = bsb + (uint32_t)rown * 80
                        + (uint32_t)(ks*32 + (((lane >> 3) & 1) << 4));
            LDM_X4(bfr[nt], bd);
        }
        #pragma unroll
        for (int mi = 0; mi < 2; mi++)
            #pragma unroll
            for (int nj = 0; nj < 8; nj++)
                MMA16816(acc[mi][nj], a[mi],
                         bfr[nj >> 1][(nj & 1)*2], bfr[nj >> 1][(nj & 1)*2 + 1]);
    }
}

// ---------------- K6: mma.sync W2 GEMM (h1-gen fused, split bf16) -------
__global__ void __launch_bounds__(256, 2)
k_mlp2m(const float* __restrict__ yts, const float* __restrict__ b2) {
    __shared__ float s_t[128];
    __shared__ float s_D[3*HID];
    __shared__ float s_b2[128];
    __shared__ __align__(16) __nv_bfloat16 As[2][128*AROW];
    __shared__ __align__(16) __nv_bfloat16 Bs[2][128*AROW];

    int tid = threadIdx.x, lane = tid & 31, wid = tid >> 5;
    int m0 = blockIdx.x * 128;
    int n0 = blockIdx.y * 128;
    int b = m0 >> 10;
    int m0w = (wid & 3) * 32;
    int n0w = (wid >> 2) * 64;

    if (tid < 128) s_t[tid] = yts[b*TT + (m0 & 1023) + tid];
    for (int i = tid; i < 3*HID; i += 256) s_D[i] = g_Dm[b*3*HID + i];
    if (tid < 128) s_b2[tid] = b2[n0 + tid];
    __syncthreads();

    uint32_t as0 = smem_u32(&As[0][0]), as1 = smem_u32(&As[1][0]);
    uint32_t bs0 = smem_u32(&Bs[0][0]), bs1 = smem_u32(&Bs[1][0]);

    int grow = tid >> 1;
    int gkh  = (tid & 1) << 4;          // 0/16
    float t = s_t[grow];

    float acc[2][8][4];
    #pragma unroll
    for (int mi = 0; mi < 2; mi++)
        #pragma unroll
        for (int nj = 0; nj < 8; nj++)
            #pragma unroll
            for (int q = 0; q < 4; q++) acc[mi][nj][q] = 0.f;

    // ---- producers ----
    auto genA = [&](int kk, uint32_t asb) {
        int third = kk >> 4;
        int kloc = ((kk & 15) << 5) + gkh;
        bool lo = (third == 1);
        uint32_t p[8];
        #pragma unroll
        for (int j2 = 0; j2 < 8; j2++) {
            float f[2];
            #pragma unroll
            for (int q = 0; q < 2; q++) {
                int k = kloc + j2*2 + q;
                float v = fmaf(t, fmaf(t, s_D[1024 + k], s_D[512 + k]), s_D[k]);
                v = fmaxf(v, 0.f);
                if (lo) v = v - __bfloat162float(__float2bfloat16_rn(v));
                f[q] = v;
            }
            p[j2] = pack2(f[0], f[1]);
        }
        uint32_t d = asb + (uint32_t)grow*80 + (uint32_t)(gkh << 1);
        asm volatile("st.shared.v4.b32 [%0], {%1,%2,%3,%4};"
                     :: "r"(d), "r"(p[0]), "r"(p[1]), "r"(p[2]), "r"(p[3]));
        asm volatile("st.shared.v4.b32 [%0+16], {%1,%2,%3,%4};"
                     :: "r"(d), "r"(p[4]), "r"(p[5]), "r"(p[6]), "r"(p[7]));
    };
    auto loadB = [&](int kk, uint32_t bsb) {
        #pragma unroll
        for (int i = 0; i < 2; i++) {
            int u = tid + (i << 8);
            int n = u >> 2, q = u & 3;
            uint32_t d = bsb + (uint32_t)n*80 + (uint32_t)(q << 4);
            const char* s = (const char*)g_B2
                + ((size_t)(n0 + n)*KP + (size_t)kk*32)*2 + q*16;
            CP16(d, s);
        }
    };

    genA(0, as0); loadB(0, bs0); CP_COMMIT();
    for (int kk = 0; kk < NKC; kk++) {
        int buf = kk & 1;
        if (kk + 1 < NKC) {
            genA(kk + 1, buf ? as0 : as1);
            loadB(kk + 1, buf ? bs0 : bs1);
            CP_COMMIT();
            CP_WAIT(1);
        } else {
            CP_WAIT(0);
        }
        __syncthreads();
        mma_compute_chunk(acc, buf ? as1 : as0, buf ? bs1 : bs0, m0w, n0w, lane);
        __syncthreads();
    }

    // ---- epilogue: relu + bias, split to bf16 hi/lo, store H2 ----
    #pragma unroll
    for (int mi = 0; mi < 2; mi++) {
        #pragma unroll
        for (int nj = 0; nj < 8; nj++) {
            int cl = n0w + nj*8 + (lane & 3)*2;
            int rg = m0 + m0w + mi*16 + (lane >> 2);
            #pragma unroll
            for (int half = 0; half < 2; half++) {
                int r = rg + half*8;
                float f0 = fmaxf(acc[mi][nj][half*2 + 0] + s_b2[cl], 0.f);
                float f1 = fmaxf(acc[mi][nj][half*2 + 1] + s_b2[cl + 1], 0.f);
                float h0 = __bfloat162float(__float2bfloat16_rn(f0));
                float h1 = __bfloat162float(__float2bfloat16_rn(f1));
                size_t o = ((size_t)r*HID + n0 + cl) * 2;
                *reinterpret_cast<uint32_t*>((char*)g_H2h + o) = pack2(h0, h1);
                *reinterpret_cast<uint32_t*>((char*)g_H2l + o) = pack2(f0 - h0, f1 - h1);
            }
        }
    }
}

// ---------------- K7: mma.sync W3 GEMM (split bf16) ---------------------
__global__ void __launch_bounds__(256, 2)
k_mlp3m(const float* __restrict__ b3, float* __restrict__ out) {
    __shared__ float s_b3[128];
    __shared__ __align__(16) __nv_bfloat16 As[2][128*AROW];
    __shared__ __align__(16) __nv_bfloat16 Bs[2][128*AROW];

    int tid = threadIdx.x, lane = tid & 31, wid = tid >> 5;
    int m0 = blockIdx.x * 128;
    int m0w = (wid & 3) * 32;
    int n0w = (wid >> 2) * 64;

    if (tid < 128) s_b3[tid] = b3[tid];
    __syncthreads();

    uint32_t as0 = smem_u32(&As[0][0]), as1 = smem_u32(&As[1][0]);
    uint32_t bs0 = smem_u32(&Bs[0][0]), bs1 = smem_u32(&Bs[1][0]);

    float acc[2][8][4];
    #pragma unroll
    for (int mi = 0; mi < 2; mi++)
        #pragma unroll
        for (int nj = 0; nj < 8; nj++)
            #pragma unroll
            for (int q = 0; q < 4; q++) acc[mi][nj][q] = 0.f;

    auto loadA = [&](int kk, uint32_t asb) {
        int third = kk >> 4;
        const char* asrc = (third == 1) ? (const char*)g_H2l : (const char*)g_H2h;
        int kloc = (kk & 15) << 5;
        #pragma unroll
        for (int i = 0; i < 2; i++) {
            int u = tid + (i << 8);
            int row = u >> 2, q = u & 3;
            uint32_t d = asb + (uint32_t)row*80 + (uint32_t)(q << 4);
            const char* s = asrc + ((size_t)(m0 + row)*HID + kloc)*2 + q*16;
            CP16(d, s);
        }
    };
    auto loadB = [&](int kk, uint32_t bsb) {
        #pragma unroll
        for (int i = 0; i < 2; i++) {
            int u = tid + (i << 8);
            int n = u >> 2, q = u & 3;
            uint32_t d = bsb + (uint32_t)n*80 + (uint32_t)(q << 4);
            const char* s = (const char*)g_B3
                + ((size_t)n*KP + (size_t)kk*32)*2 + q*16;
            CP16(d, s);
        }
    };

    loadA(0, as0); loadB(0, bs0); CP_COMMIT();
    for (int kk = 0; kk < NKC; kk++) {
        int buf = kk & 1;
        if (kk + 1 < NKC) {
            loadA(kk + 1, buf ? as0 : as1);
            loadB(kk + 1, buf ? bs0 : bs1);
            CP_COMMIT();
            CP_WAIT(1);
        } else {
            CP_WAIT(0);
        }
        __syncthreads();
        mma_compute_chunk(acc, buf ? as1 : as0, buf ? bs1 : bs0, m0w, n0w, lane);
        __syncthreads();
    }

    #pragma unroll
    for (int mi = 0; mi < 2; mi++) {
        #pragma unroll
        for (int nj = 0; nj < 8; nj++) {
            int cl = n0w + nj*8 + (lane & 3)*2;
            int rg = m0 + m0w + mi*16 + (lane >> 2);
            #pragma unroll
            for (int half = 0; half < 2; half++) {
                int r = rg + half*8;
                float2 v;
                v.x = acc[mi][nj][half*2 + 0] + s_b3[cl];
                v.y = acc[mi][nj][half*2 + 1] + s_b3[cl + 1];
                *reinterpret_cast<float2*>(&out[(size_t)r*DD + cl]) = v;
            }
        }
    }
}

// ---------------- launch -------------------------------------------------
extern "C" void kernel_launch(void* const* d_in, const int* in_sizes, int n_in,
                              void* d_out, int out_size) {
    const float* timesteps = (const float*)d_in[0];
    const float* X         = (const float*)d_in[1];
    const float* M         = (const float*)d_in[2];
    const float* yts       = (const float*)d_in[3];
    const float* w_te      = (const float*)d_in[4];
    const float* b_te      = (const float*)d_in[5];
    const float* query     = (const float*)d_in[6];
    const float* W_q       = (const float*)d_in[7];
    const float* b_q       = (const float*)d_in[8];
    const float* W_k       = (const float*)d_in[9];
    const float* b_k       = (const float*)d_in[10];
    const float* W_o       = (const float*)d_in[11];
    const float* b_o       = (const float*)d_in[12];
    const float* W1        = (const float*)d_in[13];
    const float* b1        = (const float*)d_in[14];
    const float* W2        = (const float*)d_in[15];
    const float* b2        = (const float*)d_in[16];
    const float* W3        = (const float*)d_in[17];
    const float* b3        = (const float*)d_in[18];
    float* out = (float*)d_out;

    k_setup_q<<<6, 256>>>(query, W_q, b_q);
    k_prepW<<<256, 256>>>(W2, W3);
    k_setup_A<<<48, 256>>>(W_k);
    k_setup_misc<<<4, 256>>>(b_k, w_te, b_te, W_o, b_o);
    k_scores<<<BB*LL/256, 256>>>(timesteps);
    k_att_partial<<<SPL*BB, 256>>>(X, M);
    k_att_reduce<<<BB*HP, 256>>>();
    k_coeffs<<<BB, 256>>>(W_o, W1, b1);
    k_mlp2m<<<dim3(BB*TT/128, 4), 256>>>(yts, b2);
    k_mlp3m<<<BB*TT/128, 256>>>(b3, out);
}

// round 6
// speedup vs baseline: 1.9832x; 1.0097x over previous
#include <cuda_runtime.h>
#include <cuda_bf16.h>
#include <math.h>
#include <stdint.h>

#define BB 64
#define LL 2048
#define TT 1024
#define DD 128
#define EE 512
#define HH 8
#define PP 3
#define HP 24
#define LAT 256
#define HID 512
#define NSIN 64
#define SPL 8
#define LSP (LL/SPL)
#define KP 1536          // tripled K for split GEMM
#define NKC 48           // K' chunks of 32
#define AROW 40          // padded smem row (bf16 elems) = 80 bytes

// ---------------- static device scratch (no allocations) ----------------
__device__ float g_q[PP*EE];
__device__ float g_A[EE*HP];
__device__ float g_lin[HP];
__device__ float g_off[HP];
__device__ float g_ws[NSIN];
__device__ float g_bs[NSIN];
__device__ float g_Asin[NSIN*HP];
__device__ float g_bcp[8*LAT];
__device__ float g_scores[BB*LL*HP];
__device__ unsigned int g_maxu[BB*HP];
__device__ float g_part[SPL*BB*HP*256];
__device__ float g_Dm[BB*3*HID];
__device__ __align__(16) __nv_bfloat16 g_B2[512*KP];         // W2' split, [n][k']
__device__ __align__(16) __nv_bfloat16 g_B3[128*KP];         // W3' split, [n][k']
__device__ __align__(16) __nv_bfloat16 g_H2h[(size_t)BB*TT*HID];
__device__ __align__(16) __nv_bfloat16 g_H2l[(size_t)BB*TT*HID];

__device__ __forceinline__ unsigned int enc_f(float f) {
    unsigned int u = __float_as_uint(f);
    return (u & 0x80000000u) ? ~u : (u | 0x80000000u);
}
__device__ __forceinline__ float dec_f(unsigned int u) {
    return (u & 0x80000000u) ? __uint_as_float(u & 0x7FFFFFFFu)
                             : __uint_as_float(~u);
}

// ---------------- PTX helpers -------------------------------------------
__device__ __forceinline__ uint32_t smem_u32(const void* p) {
    uint32_t a;
    asm("{ .reg .u64 t; cvta.to.shared.u64 t, %1; cvt.u32.u64 %0, t; }"
        : "=r"(a) : "l"(p));
    return a;
}
__device__ __forceinline__ uint32_t pack2(float a, float b) {
    __nv_bfloat162 h = __floats2bfloat162_rn(a, b);
    return *reinterpret_cast<uint32_t*>(&h);
}

#define CP16(dst, src) \
    asm volatile("cp.async.cg.shared.global [%0], [%1], 16;" :: "r"(dst), "l"(src))
#define CP_COMMIT() asm volatile("cp.async.commit_group;" ::: "memory")
#define CP_WAIT(n)  asm volatile("cp.async.wait_group %0;" :: "n"(n) : "memory")

#define LDM_X4(r, addr) \
    asm volatile("ldmatrix.sync.aligned.m8n8.x4.shared.b16 {%0,%1,%2,%3}, [%4];" \
        : "=r"((r)[0]), "=r"((r)[1]), "=r"((r)[2]), "=r"((r)[3]) : "r"(addr))

#define MMA16816(c, a, b0, b1) \
    asm volatile("mma.sync.aligned.m16n8k16.row.col.f32.bf16.bf16.f32 " \
        "{%0,%1,%2,%3}, {%4,%5,%6,%7}, {%8,%9}, {%0,%1,%2,%3};" \
        : "+f"((c)[0]), "+f"((c)[1]), "+f"((c)[2]), "+f"((c)[3]) \
        : "r"((a)[0]), "r"((a)[1]), "r"((a)[2]), "r"((a)[3]), "r"(b0), "r"(b1))

// ---------------- setup kernels -----------------------------------------
__global__ void k_setup_q(const float* __restrict__ query,
                          const float* __restrict__ W_q,
                          const float* __restrict__ b_q) {
    int idx = blockIdx.x * 256 + threadIdx.x;   // < 1536
    int p = idx / EE, e = idx % EE;
    float acc = b_q[e];
    for (int i = 0; i < EE; i++)
        acc = fmaf(query[p*EE + i], W_q[i*EE + e], acc);
    g_q[idx] = acc;
}

__global__ void k_setup_A(const float* __restrict__ W_k) {
    int idx = blockIdx.x * 256 + threadIdx.x;   // < 12288
    int e = idx / HP, hp = idx % HP;
    int h = hp / PP, p = hp % PP;
    float acc = 0.f;
    #pragma unroll 4
    for (int j = 0; j < 64; j++)
        acc = fmaf(W_k[e*EE + h*64 + j], g_q[p*EE + h*64 + j], acc);
    g_A[idx] = acc * 0.125f;
}

__global__ void k_setup_misc(const float* __restrict__ b_k,
                             const float* __restrict__ w_te,
                             const float* __restrict__ b_te) {
    int tid = threadIdx.x;
    int bid = blockIdx.x;
    if (bid == 0) {
        if (tid < HP) {
            int hp = tid, h = hp / PP, p = hp % PP;
            float lin = 0.f, off = 0.f;
            for (int j = 0; j < 64; j++)
                off = fmaf(g_q[p*EE + h*64 + j], b_k[h*64 + j], off);
            off *= 0.125f;
            for (int e = 0; e < EE; e++) {
                if ((e & 7) != 0) {
                    float a = g_A[e*HP + hp];
                    lin = fmaf(w_te[e], a, lin);
                    off = fmaf(b_te[e], a, off);
                }
            }
            g_lin[hp] = lin; g_off[hp] = off;
        }
        if (tid < NSIN) { g_ws[tid] = w_te[8*tid]; g_bs[tid] = b_te[8*tid]; }
    } else {
        for (int idx = tid; idx < NSIN*HP; idx += 256) {
            int j = idx / HP, hp = idx % HP;
            g_Asin[idx] = g_A[(8*j)*HP + hp];
        }
        for (int i = tid; i < BB*HP; i += 256) g_maxu[i] = 0u;
    }
}

// ---------------- bconst partials: coalesced column sums ----------------
__global__ void k_bcpart(const float* __restrict__ W_o) {
    int h = blockIdx.x;           // 0..7
    int n = threadIdx.x;          // 0..255
    float acc = 0.f;
    const float* base = W_o + (size_t)(h*256 + 128)*LAT + n;
    #pragma unroll 8
    for (int c = 0; c < DD; c++)
        acc += base[(size_t)c*LAT];
    g_bcp[h*LAT + n] = acc;
}

// ---------------- W2'/W3' split prep (smem-tiled transpose) -------------
__global__ void k_prepW(const float* __restrict__ W2,
                        const float* __restrict__ W3) {
    __shared__ float s_tile[64][65];
    int bid = blockIdx.x;         // 0..79
    int tid = threadIdx.x;
    int c = tid & 63, rloc = tid >> 6;

    const float* src; __nv_bfloat16* dst;
    int tk, tn, src_cols;
    if (bid < 64) { tk = bid >> 3; tn = bid & 7; src = W2; dst = g_B2; src_cols = 512; }
    else          { int l = bid - 64; tk = l >> 1; tn = l & 1; src = W3; dst = g_B3; src_cols = 128; }

    #pragma unroll
    for (int i = 0; i < 16; i++) {
        int row = rloc + i*4;
        s_tile[row][c] = src[(size_t)(tk*64 + row)*src_cols + tn*64 + c];
    }
    __syncthreads();
    // write transposed: thread varies k (c) fastest -> coalesced bf16 rows
    #pragma unroll
    for (int i = 0; i < 16; i++) {
        int n = rloc + i*4;
        float w = s_tile[c][n];
        __nv_bfloat16 h = __float2bfloat16_rn(w);
        __nv_bfloat16 l = __float2bfloat16_rn(w - __bfloat162float(h));
        __nv_bfloat16* row = dst + (size_t)(tn*64 + n)*KP + tk*64 + c;
        row[0] = h; row[512] = h; row[1024] = l;
    }
}

// ---------------- K2: scores + per-(b,hp) max ---------------------------
__global__ void k_scores(const float* __restrict__ timesteps) {
    __shared__ float s_Asin[NSIN*HP];
    __shared__ float s_lin[HP], s_off[HP];
    __shared__ float s_ws[NSIN], s_bs[NSIN];
    __shared__ unsigned int s_max[HP];
    int tid = threadIdx.x;
    int g = blockIdx.x * 256 + tid;
    int b = g / LL;
    for (int i = tid; i < NSIN*HP; i += 256) s_Asin[i] = g_Asin[i];
    if (tid < HP) { s_lin[tid] = g_lin[tid]; s_off[tid] = g_off[tid]; s_max[tid] = 0u; }
    if (tid < NSIN) { s_ws[tid] = g_ws[tid]; s_bs[tid] = g_bs[tid]; }
    __syncthreads();

    float t = timesteps[g];
    float acc[HP];
    #pragma unroll
    for (int hp = 0; hp < HP; hp++) acc[hp] = fmaf(t, s_lin[hp], s_off[hp]);
    for (int j = 0; j < NSIN; j++) {
        float s = __sinf(fmaf(t, s_ws[j], s_bs[j]));
        #pragma unroll
        for (int hp = 0; hp < HP; hp++)
            acc[hp] = fmaf(s, s_Asin[j*HP + hp], acc[hp]);
    }
    #pragma unroll
    for (int hp = 0; hp < HP; hp++) {
        g_scores[g*HP + hp] = acc[hp];
        atomicMax(&s_max[hp], enc_f(acc[hp]));
    }
    __syncthreads();
    if (tid < HP) atomicMax(&g_maxu[b*HP + tid], s_max[tid]);
}

// ---------------- K3: attention partial sums ----------------------------
__global__ void k_att_partial(const float* __restrict__ X,
                              const float* __restrict__ M) {
    __shared__ float s_m[HP];
    __shared__ float s_w[64*HP];
    int tid = threadIdx.x;
    int b  = blockIdx.x / SPL;
    int sp = blockIdx.x % SPL;
    int l0 = sp * LSP;
    if (tid < HP) s_m[tid] = dec_f(g_maxu[b*HP + tid]);
    float acc[HP];
    #pragma unroll
    for (int hp = 0; hp < HP; hp++) acc[hp] = 0.f;
    int c = tid;

    for (int ch = 0; ch < LSP; ch += 64) {
        __syncthreads();
        for (int i = tid; i < 64*HP; i += 256) {
            int li = i / HP, hp = i % HP;
            float sc = g_scores[(b*LL + l0 + ch + li)*HP + hp];
            s_w[i] = __expf(sc - s_m[hp]);
        }
        __syncthreads();
        for (int li = 0; li < 64; li++) {
            int l = l0 + ch + li;
            float f;
            if (c < DD) {
                float xv = X[((long)b*LL + l)*DD + c];
                float mv = M[((long)b*LL + l)*DD + c];
                f = xv * mv;
            } else {
                f = M[((long)b*LL + l)*DD + (c - DD)];
            }
            #pragma unroll
            for (int hp = 0; hp < HP; hp++)
                acc[hp] = fmaf(s_w[li*HP + hp], f, acc[hp]);
        }
    }
    for (int hp = 0; hp < HP; hp++)
        g_part[(((sp*BB) + b)*HP + hp)*256 + c] = acc[hp];
}

// ---------------- K5: x1 (with fused reduce), coeffs, D-matrices --------
__global__ void k_coeffs(const float* __restrict__ W_o,
                         const float* __restrict__ W1,
                         const float* __restrict__ b1,
                         const float* __restrict__ b_o) {
    __shared__ float s_x1[HP*DD];
    __shared__ float s_cf[PP*LAT];
    int tid = threadIdx.x;
    int b = blockIdx.x;
    for (int i = tid; i < HP*DD; i += 256) {
        int hp = i / DD, c = i % DD;
        float num = 0.f, den = 0.f;
        #pragma unroll
        for (int sp = 0; sp < SPL; sp++) {
            int base = (((sp*BB) + b)*HP + hp)*256;
            num += g_part[base + c];
            den += g_part[base + 128 + c];
        }
        s_x1[i] = num / den;
    }
    __syncthreads();
    {
        int n = tid;
        float bc = b_o[n];
        #pragma unroll
        for (int j = 0; j < 8; j++) bc += g_bcp[j*LAT + n];
        float a0 = bc, a1 = bc, a2 = bc;
        for (int h = 0; h < HH; h++) {
            #pragma unroll 4
            for (int c = 0; c < DD; c++) {
                float wv = W_o[(h*256 + c)*LAT + n];
                a0 = fmaf(s_x1[(h*PP + 0)*DD + c], wv, a0);
                a1 = fmaf(s_x1[(h*PP + 1)*DD + c], wv, a1);
                a2 = fmaf(s_x1[(h*PP + 2)*DD + c], wv, a2);
            }
        }
        s_cf[0*LAT + n] = a0; s_cf[1*LAT + n] = a1; s_cf[2*LAT + n] = a2;
    }
    __syncthreads();
    for (int idx = tid; idx < 3*HID; idx += 256) {
        int k = idx / HID, j = idx % HID;
        float acc = (k == 0) ? b1[j] : 0.f;
        #pragma unroll 4
        for (int n = 0; n < LAT; n++)
            acc = fmaf(s_cf[k*LAT + n], W1[n*HID + j], acc);
        g_Dm[(b*3 + k)*HID + j] = acc;
    }
}

// ---------------- shared compute core for mma GEMMs ---------------------
__device__ __forceinline__ void mma_compute_chunk(
    float acc[2][8][4], uint32_t asb, uint32_t bsb,
    int m0w, int n0w, int lane)
{
    #pragma unroll
    for (int ks = 0; ks < 2; ks++) {
        uint32_t a[2][4];
        #pragma unroll
        for (int mi = 0; mi < 2; mi++) {
            uint32_t ad = asb + (uint32_t)(m0w + mi*16 + (lane & 15)) * 80
                        + (uint32_t)(ks*32 + ((lane >> 4) << 4));
            LDM_X4(a[mi], ad);
        }
        uint32_t bfr[4][4];
        #pragma unroll
        for (int nt = 0; nt < 4; nt++) {
            int rown = n0w + nt*16 + ((lane >> 4) << 3) + (lane & 7);
            uint32_t bd = bsb + (uint32_t)rown * 80
                        + (uint32_t)(ks*32 + (((lane >> 3) & 1) << 4));
            LDM_X4(bfr[nt], bd);
        }
        #pragma unroll
        for (int mi = 0; mi < 2; mi++)
            #pragma unroll
            for (int nj = 0; nj < 8; nj++)
                MMA16816(acc[mi][nj], a[mi],
                         bfr[nj >> 1][(nj & 1)*2], bfr[nj >> 1][(nj & 1)*2 + 1]);
    }
}

// ---------------- K6: mma.sync W2 GEMM (h1-gen fused, split bf16) -------
__global__ void __launch_bounds__(256, 2)
k_mlp2m(const float* __restrict__ yts, const float* __restrict__ b2) {
    __shared__ float s_t[128];
    __shared__ float s_D[3*HID];
    __shared__ float s_b2[128];
    __shared__ __align__(16) __nv_bfloat16 s_buf[2][2][128*AROW];   // 40960 B

    int tid = threadIdx.x, lane = tid & 31, wid = tid >> 5;
    int m0 = blockIdx.x * 128;
    int n0 = blockIdx.y * 128;
    int b = m0 >> 10;
    int m0w = (wid & 3) * 32;
    int n0w = (wid >> 2) * 64;

    if (tid < 128) s_t[tid] = yts[b*TT + (m0 & 1023) + tid];
    for (int i = tid; i < 3*HID; i += 256) s_D[i] = g_Dm[b*3*HID + i];
    if (tid < 128) s_b2[tid] = b2[n0 + tid];
    __syncthreads();

    uint32_t as0 = smem_u32(&s_buf[0][0][0]), as1 = smem_u32(&s_buf[0][1][0]);
    uint32_t bs0 = smem_u32(&s_buf[1][0][0]), bs1 = smem_u32(&s_buf[1][1][0]);

    int grow = tid >> 1;
    int gkh  = (tid & 1) << 4;          // 0/16
    float t = s_t[grow];

    float acc[2][8][4];
    #pragma unroll
    for (int mi = 0; mi < 2; mi++)
        #pragma unroll
        for (int nj = 0; nj < 8; nj++)
            #pragma unroll
            for (int q = 0; q < 4; q++) acc[mi][nj][q] = 0.f;

    // ---- producers ----
    auto genA = [&](int kk, uint32_t asb) {
        int third = kk >> 4;
        int kloc = ((kk & 15) << 5) + gkh;
        bool lo = (third == 1);
        uint32_t p[8];
        #pragma unroll
        for (int j2 = 0; j2 < 8; j2++) {
            float f[2];
            #pragma unroll
            for (int q = 0; q < 2; q++) {
                int k = kloc + j2*2 + q;
                float v = fmaf(t, fmaf(t, s_D[1024 + k], s_D[512 + k]), s_D[k]);
                v = fmaxf(v, 0.f);
                if (lo) v = v - __bfloat162float(__float2bfloat16_rn(v));
                f[q] = v;
            }
            p[j2] = pack2(f[0], f[1]);
        }
        uint32_t d = asb + (uint32_t)grow*80 + (uint32_t)(gkh << 1);
        asm volatile("st.shared.v4.b32 [%0], {%1,%2,%3,%4};"
                     :: "r"(d), "r"(p[0]), "r"(p[1]), "r"(p[2]), "r"(p[3]));
        asm volatile("st.shared.v4.b32 [%0+16], {%1,%2,%3,%4};"
                     :: "r"(d), "r"(p[4]), "r"(p[5]), "r"(p[6]), "r"(p[7]));
    };
    auto loadB = [&](int kk, uint32_t bsb) {
        #pragma unroll
        for (int i = 0; i < 2; i++) {
            int u = tid + (i << 8);
            int n = u >> 2, q = u & 3;
            uint32_t d = bsb + (uint32_t)n*80 + (uint32_t)(q << 4);
            const char* s = (const char*)g_B2
                + ((size_t)(n0 + n)*KP + (size_t)kk*32)*2 + q*16;
            CP16(d, s);
        }
    };

    genA(0, as0); loadB(0, bs0); CP_COMMIT();
    for (int kk = 0; kk < NKC; kk++) {
        int buf = kk & 1;
        if (kk + 1 < NKC) {
            genA(kk + 1, buf ? as0 : as1);
            loadB(kk + 1, buf ? bs0 : bs1);
            CP_COMMIT();
            CP_WAIT(1);
        } else {
            CP_WAIT(0);
        }
        __syncthreads();
        mma_compute_chunk(acc, buf ? as1 : as0, buf ? bs1 : bs0, m0w, n0w, lane);
        __syncthreads();
    }

    // ---- epilogue: relu+bias, split hi/lo, smem-staged coalesced stores ----
    char* stg = (char*)&s_buf[0][0][0];      // 128 x 136 bf16 = 34816 B
    const int PADR = 136;
    #pragma unroll
    for (int round = 0; round < 2; round++) {
        #pragma unroll
        for (int mi = 0; mi < 2; mi++) {
            #pragma unroll
            for (int nj = 0; nj < 8; nj++) {
                int cl = n0w + nj*8 + (lane & 3)*2;
                #pragma unroll
                for (int half = 0; half < 2; half++) {
                    int r = m0w + mi*16 + (lane >> 2) + half*8;
                    float f0 = fmaxf(acc[mi][nj][half*2 + 0] + s_b2[cl], 0.f);
                    float f1 = fmaxf(acc[mi][nj][half*2 + 1] + s_b2[cl + 1], 0.f);
                    float h0 = __bfloat162float(__float2bfloat16_rn(f0));
                    float h1 = __bfloat162float(__float2bfloat16_rn(f1));
                    uint32_t v = (round == 0) ? pack2(h0, h1)
                                              : pack2(f0 - h0, f1 - h1);
                    *reinterpret_cast<uint32_t*>(stg + (r*PADR + cl)*2) = v;
                }
            }
        }
        __syncthreads();
        char* dstb = (round == 0) ? (char*)g_H2h : (char*)g_H2l;
        #pragma unroll
        for (int ps = 0; ps < 8; ps++) {
            int u = ps*256 + tid;
            int row = u >> 4, ch = u & 15;
            uint4 v = *reinterpret_cast<uint4*>(stg + row*PADR*2 + ch*16);
            *reinterpret_cast<uint4*>(dstb + ((size_t)(m0 + row)*HID + n0)*2 + ch*16) = v;
        }
        __syncthreads();
    }
}

// ---------------- K7: mma.sync W3 GEMM (split bf16) ---------------------
__global__ void __launch_bounds__(256, 2)
k_mlp3m(const float* __restrict__ b3, float* __restrict__ out) {
    __shared__ float s_b3[128];
    __shared__ __align__(16) __nv_bfloat16 As[2][128*AROW];
    __shared__ __align__(16) __nv_bfloat16 Bs[2][128*AROW];

    int tid = threadIdx.x, lane = tid & 31, wid = tid >> 5;
    int m0 = blockIdx.x * 128;
    int m0w = (wid & 3) * 32;
    int n0w = (wid >> 2) * 64;

    if (tid < 128) s_b3[tid] = b3[tid];
    __syncthreads();

    uint32_t as0 = smem_u32(&As[0][0]), as1 = smem_u32(&As[1][0]);
    uint32_t bs0 = smem_u32(&Bs[0][0]), bs1 = smem_u32(&Bs[1][0]);

    float acc[2][8][4];
    #pragma unroll
    for (int mi = 0; mi < 2; mi++)
        #pragma unroll
        for (int nj = 0; nj < 8; nj++)
            #pragma unroll
            for (int q = 0; q < 4; q++) acc[mi][nj][q] = 0.f;

    auto loadA = [&](int kk, uint32_t asb) {
        int third = kk >> 4;
        const char* asrc = (third == 1) ? (const char*)g_H2l : (const char*)g_H2h;
        int kloc = (kk & 15) << 5;
        #pragma unroll
        for (int i = 0; i < 2; i++) {
            int u = tid + (i << 8);
            int row = u >> 2, q = u & 3;
            uint32_t d = asb + (uint32_t)row*80 + (uint32_t)(q << 4);
            const char* s = asrc + ((size_t)(m0 + row)*HID + kloc)*2 + q*16;
            CP16(d, s);
        }
    };
    auto loadB = [&](int kk, uint32_t bsb) {
        #pragma unroll
        for (int i = 0; i < 2; i++) {
            int u = tid + (i << 8);
            int n = u >> 2, q = u & 3;
            uint32_t d = bsb + (uint32_t)n*80 + (uint32_t)(q << 4);
            const char* s = (const char*)g_B3
                + ((size_t)n*KP + (size_t)kk*32)*2 + q*16;
            CP16(d, s);
        }
    };

    loadA(0, as0); loadB(0, bs0); CP_COMMIT();
    for (int kk = 0; kk < NKC; kk++) {
        int buf = kk & 1;
        if (kk + 1 < NKC) {
            loadA(kk + 1, buf ? as0 : as1);
            loadB(kk + 1, buf ? bs0 : bs1);
            CP_COMMIT();
            CP_WAIT(1);
        } else {
            CP_WAIT(0);
        }
        __syncthreads();
        mma_compute_chunk(acc, buf ? as1 : as0, buf ? bs1 : bs0, m0w, n0w, lane);
        __syncthreads();
    }

    #pragma unroll
    for (int mi = 0; mi < 2; mi++) {
        #pragma unroll
        for (int nj = 0; nj < 8; nj++) {
            int cl = n0w + nj*8 + (lane & 3)*2;
            int rg = m0 + m0w + mi*16 + (lane >> 2);
            #pragma unroll
            for (int half = 0; half < 2; half++) {
                int r = rg + half*8;
                float2 v;
                v.x = acc[mi][nj][half*2 + 0] + s_b3[cl];
                v.y = acc[mi][nj][half*2 + 1] + s_b3[cl + 1];
                *reinterpret_cast<float2*>(&out[(size_t)r*DD + cl]) = v;
            }
        }
    }
}

// ---------------- launch -------------------------------------------------
extern "C" void kernel_launch(void* const* d_in, const int* in_sizes, int n_in,
                              void* d_out, int out_size) {
    const float* timesteps = (const float*)d_in[0];
    const float* X         = (const float*)d_in[1];
    const float* M         = (const float*)d_in[2];
    const float* yts       = (const float*)d_in[3];
    const float* w_te      = (const float*)d_in[4];
    const float* b_te      = (const float*)d_in[5];
    const float* query     = (const float*)d_in[6];
    const float* W_q       = (const float*)d_in[7];
    const float* b_q       = (const float*)d_in[8];
    const float* W_k       = (const float*)d_in[9];
    const float* b_k       = (const float*)d_in[10];
    const float* W_o       = (const float*)d_in[11];
    const float* b_o       = (const float*)d_in[12];
    const float* W1        = (const float*)d_in[13];
    const float* b1        = (const float*)d_in[14];
    const float* W2        = (const float*)d_in[15];
    const float* b2        = (const float*)d_in[16];
    const float* W3        = (const float*)d_in[17];
    const float* b3        = (const float*)d_in[18];
    float* out = (float*)d_out;

    k_setup_q<<<6, 256>>>(query, W_q, b_q);
    k_prepW<<<80, 256>>>(W2, W3);
    k_bcpart<<<8, 256>>>(W_o);
    k_setup_A<<<48, 256>>>(W_k);
    k_setup_misc<<<2, 256>>>(b_k, w_te, b_te);
    k_scores<<<BB*LL/256, 256>>>(timesteps);
    k_att_partial<<<SPL*BB, 256>>>(X, M);
    k_coeffs<<<BB, 256>>>(W_o, W1, b1, b_o);
    k_mlp2m<<<dim3(BB*TT/128, 4), 256>>>(yts, b2);
    k_mlp3m<<<BB*TT/128, 256>>>(b3, out);
}

// round 9
// speedup vs baseline: 2.0439x; 1.0306x over previous
#include <cuda_runtime.h>
#include <cuda_bf16.h>
#include <math.h>
#include <stdint.h>

#define BB 64
#define LL 2048
#define TT 1024
#define DD 128
#define EE 512
#define HH 8
#define PP 3
#define HP 24
#define LAT 256
#define HID 512
#define NSIN 64
#define SPL 8
#define LSP (LL/SPL)
#define KP 1536          // tripled K for W2 split GEMM
#define KP3 1024         // [Bh|Bl] for W3
#define NKC2 24          // K' chunks of 64 for mlp2
#define ROWB 144         // A/B smem row bytes (64 bf16 + 8 pad)
#define ROWW 272         // wide-B smem row bytes (128 bf16 + 8 pad)

// ---------------- static device scratch (no allocations) ----------------
__device__ float g_q[PP*EE];
__device__ float g_A[EE*HP];
__device__ float g_lin[HP];
__device__ float g_off[HP];
__device__ float g_ws[NSIN];
__device__ float g_bs[NSIN];
__device__ float g_Asin[NSIN*HP];
__device__ float g_bcp[8*LAT];
__device__ float g_scores[BB*LL*HP];
__device__ unsigned int g_maxu[BB*HP];
__device__ float g_part[SPL*BB*HP*256];
__device__ float g_Dm[BB*3*HID];
__device__ __align__(16) __nv_bfloat16 g_B2[512*KP];          // [n][Bh|Bh|Bl]
__device__ __align__(16) __nv_bfloat16 g_B3[128*KP3];         // [n][Bh|Bl]
__device__ __align__(16) __nv_bfloat16 g_H2h[(size_t)BB*TT*HID];
__device__ __align__(16) __nv_bfloat16 g_H2l[(size_t)BB*TT*HID];

__device__ __forceinline__ unsigned int enc_f(float f) {
    unsigned int u = __float_as_uint(f);
    return (u & 0x80000000u) ? ~u : (u | 0x80000000u);
}
__device__ __forceinline__ float dec_f(unsigned int u) {
    return (u & 0x80000000u) ? __uint_as_float(u & 0x7FFFFFFFu)
                             : __uint_as_float(~u);
}

// ---------------- PTX helpers -------------------------------------------
__device__ __forceinline__ uint32_t smem_u32(const void* p) {
    uint32_t a;
    asm("{ .reg .u64 t; cvta.to.shared.u64 t, %1; cvt.u32.u64 %0, t; }"
        : "=r"(a) : "l"(p));
    return a;
}
__device__ __forceinline__ uint32_t pack2(float a, float b) {
    __nv_bfloat162 h = __floats2bfloat162_rn(a, b);
    return *reinterpret_cast<uint32_t*>(&h);
}

#define CP16(dst, src) \
    asm volatile("cp.async.cg.shared.global [%0], [%1], 16;" :: "r"(dst), "l"(src))
#define CP_COMMIT() asm volatile("cp.async.commit_group;" ::: "memory")
#define CP_WAIT(n)  asm volatile("cp.async.wait_group %0;" :: "n"(n) : "memory")

#define LDM_X4(r, addr) \
    asm volatile("ldmatrix.sync.aligned.m8n8.x4.shared.b16 {%0,%1,%2,%3}, [%4];" \
        : "=r"((r)[0]), "=r"((r)[1]), "=r"((r)[2]), "=r"((r)[3]) : "r"(addr))

#define MMA16816(c, a, b0, b1) \
    asm volatile("mma.sync.aligned.m16n8k16.row.col.f32.bf16.bf16.f32 " \
        "{%0,%1,%2,%3}, {%4,%5,%6,%7}, {%8,%9}, {%0,%1,%2,%3};" \
        : "+f"((c)[0]), "+f"((c)[1]), "+f"((c)[2]), "+f"((c)[3]) \
        : "r"((a)[0]), "r"((a)[1]), "r"((a)[2]), "r"((a)[3]), "r"(b0), "r"(b1))

// ---------------- setup kernels -----------------------------------------
__global__ void k_setup_q(const float* __restrict__ query,
                          const float* __restrict__ W_q,
                          const float* __restrict__ b_q) {
    int idx = blockIdx.x * 256 + threadIdx.x;   // < 1536
    int p = idx / EE, e = idx % EE;
    float acc = b_q[e];
    for (int i = 0; i < EE; i++)
        acc = fmaf(query[p*EE + i], W_q[i*EE + e], acc);
    g_q[idx] = acc;
}

__global__ void k_setup_A(const float* __restrict__ W_k) {
    int idx = blockIdx.x * 256 + threadIdx.x;   // < 12288
    int e = idx / HP, hp = idx % HP;
    int h = hp / PP, p = hp % PP;
    float acc = 0.f;
    #pragma unroll 4
    for (int j = 0; j < 64; j++)
        acc = fmaf(W_k[e*EE + h*64 + j], g_q[p*EE + h*64 + j], acc);
    g_A[idx] = acc * 0.125f;
}

__global__ void k_setup_misc(const float* __restrict__ b_k,
                             const float* __restrict__ w_te,
                             const float* __restrict__ b_te) {
    int tid = threadIdx.x;
    int bid = blockIdx.x;
    if (bid == 0) {
        if (tid < HP) {
            int hp = tid, h = hp / PP, p = hp % PP;
            float lin = 0.f, off = 0.f;
            for (int j = 0; j < 64; j++)
                off = fmaf(g_q[p*EE + h*64 + j], b_k[h*64 + j], off);
            off *= 0.125f;
            for (int e = 0; e < EE; e++) {
                if ((e & 7) != 0) {
                    float a = g_A[e*HP + hp];
                    lin = fmaf(w_te[e], a, lin);
                    off = fmaf(b_te[e], a, off);
                }
            }
            g_lin[hp] = lin; g_off[hp] = off;
        }
        if (tid < NSIN) { g_ws[tid] = w_te[8*tid]; g_bs[tid] = b_te[8*tid]; }
    } else {
        for (int idx = tid; idx < NSIN*HP; idx += 256) {
            int j = idx / HP, hp = idx % HP;
            g_Asin[idx] = g_A[(8*j)*HP + hp];
        }
        for (int i = tid; i < BB*HP; i += 256) g_maxu[i] = 0u;
    }
}

// ---------------- bconst partials ---------------------------------------
__global__ void k_bcpart(const float* __restrict__ W_o) {
    int h = blockIdx.x;           // 0..7
    int n = threadIdx.x;          // 0..255
    float acc = 0.f;
    const float* base = W_o + (size_t)(h*256 + 128)*LAT + n;
    #pragma unroll 8
    for (int c = 0; c < DD; c++)
        acc += base[(size_t)c*LAT];
    g_bcp[h*LAT + n] = acc;
}

// ---------------- W2'/W3' split prep (smem-tiled transpose) -------------
__global__ void k_prepW(const float* __restrict__ W2,
                        const float* __restrict__ W3) {
    __shared__ float s_tile[64][65];
    int bid = blockIdx.x;         // 0..79
    int tid = threadIdx.x;
    int c = tid & 63, rloc = tid >> 6;

    const float* src;
    int tk, tn, src_cols;
    bool isW2 = (bid < 64);
    if (isW2) { tk = bid >> 3; tn = bid & 7; src = W2; src_cols = 512; }
    else      { int l = bid - 64; tk = l >> 1; tn = l & 1; src = W3; src_cols = 128; }

    #pragma unroll
    for (int i = 0; i < 16; i++) {
        int row = rloc + i*4;
        s_tile[row][c] = src[(size_t)(tk*64 + row)*src_cols + tn*64 + c];
    }
    __syncthreads();
    #pragma unroll
    for (int i = 0; i < 16; i++) {
        int n = rloc + i*4;
        float w = s_tile[c][n];
        __nv_bfloat16 h = __float2bfloat16_rn(w);
        __nv_bfloat16 l = __float2bfloat16_rn(w - __bfloat162float(h));
        if (isW2) {
            __nv_bfloat16* row = g_B2 + (size_t)(tn*64 + n)*KP + tk*64 + c;
            row[0] = h; row[512] = h; row[1024] = l;
        } else {
            __nv_bfloat16* row = g_B3 + (size_t)(tn*64 + n)*KP3 + tk*64 + c;
            row[0] = h; row[512] = l;
        }
    }
}

// ---------------- K2: scores + per-(b,hp) max ---------------------------
__global__ void k_scores(const float* __restrict__ timesteps) {
    __shared__ float s_Asin[NSIN*HP];
    __shared__ float s_lin[HP], s_off[HP];
    __shared__ float s_ws[NSIN], s_bs[NSIN];
    __shared__ unsigned int s_max[HP];
    int tid = threadIdx.x;
    int g = blockIdx.x * 256 + tid;
    int b = g / LL;
    for (int i = tid; i < NSIN*HP; i += 256) s_Asin[i] = g_Asin[i];
    if (tid < HP) { s_lin[tid] = g_lin[tid]; s_off[tid] = g_off[tid]; s_max[tid] = 0u; }
    if (tid < NSIN) { s_ws[tid] = g_ws[tid]; s_bs[tid] = g_bs[tid]; }
    __syncthreads();

    float t = timesteps[g];
    float acc[HP];
    #pragma unroll
    for (int hp = 0; hp < HP; hp++) acc[hp] = fmaf(t, s_lin[hp], s_off[hp]);
    for (int j = 0; j < NSIN; j++) {
        float s = __sinf(fmaf(t, s_ws[j], s_bs[j]));
        #pragma unroll
        for (int hp = 0; hp < HP; hp++)
            acc[hp] = fmaf(s, s_Asin[j*HP + hp], acc[hp]);
    }
    #pragma unroll
    for (int hp = 0; hp < HP; hp++) {
        g_scores[g*HP + hp] = acc[hp];
        atomicMax(&s_max[hp], enc_f(acc[hp]));
    }
    __syncthreads();
    if (tid < HP) atomicMax(&g_maxu[b*HP + tid], s_max[tid]);
}

// ---------------- K3: attention partial sums ----------------------------
__global__ void k_att_partial(const float* __restrict__ X,
                              const float* __restrict__ M) {
    __shared__ float s_m[HP];
    __shared__ float s_w[64*HP];
    int tid = threadIdx.x;
    int b  = blockIdx.x / SPL;
    int sp = blockIdx.x % SPL;
    int l0 = sp * LSP;
    if (tid < HP) s_m[tid] = dec_f(g_maxu[b*HP + tid]);
    float acc[HP];
    #pragma unroll
    for (int hp = 0; hp < HP; hp++) acc[hp] = 0.f;
    int c = tid;

    for (int ch = 0; ch < LSP; ch += 64) {
        __syncthreads();
        for (int i = tid; i < 64*HP; i += 256) {
            int li = i / HP, hp = i % HP;
            float sc = g_scores[(b*LL + l0 + ch + li)*HP + hp];
            s_w[i] = __expf(sc - s_m[hp]);
        }
        __syncthreads();
        for (int li = 0; li < 64; li++) {
            int l = l0 + ch + li;
            float f;
            if (c < DD) {
                float xv = X[((long)b*LL + l)*DD + c];
                float mv = M[((long)b*LL + l)*DD + c];
                f = xv * mv;
            } else {
                f = M[((long)b*LL + l)*DD + (c - DD)];
            }
            #pragma unroll
            for (int hp = 0; hp < HP; hp++)
                acc[hp] = fmaf(s_w[li*HP + hp], f, acc[hp]);
        }
    }
    for (int hp = 0; hp < HP; hp++)
        g_part[(((sp*BB) + b)*HP + hp)*256 + c] = acc[hp];
}

// ---------------- K5: x1 (fused reduce), coeffs, D-matrices -------------
__global__ void k_coeffs(const float* __restrict__ W_o,
                         const float* __restrict__ W1,
                         const float* __restrict__ b1,
                         const float* __restrict__ b_o) {
    __shared__ float s_x1[HP*DD];
    __shared__ float s_cf[PP*LAT];
    int tid = threadIdx.x;
    int b = blockIdx.x;
    for (int i = tid; i < HP*DD; i += 256) {
        int hp = i / DD, c = i % DD;
        float num = 0.f, den = 0.f;
        #pragma unroll
        for (int sp = 0; sp < SPL; sp++) {
            int base = (((sp*BB) + b)*HP + hp)*256;
            num += g_part[base + c];
            den += g_part[base + 128 + c];
        }
        s_x1[i] = num / den;
    }
    __syncthreads();
    {
        int n = tid;
        float bc = b_o[n];
        #pragma unroll
        for (int j = 0; j < 8; j++) bc += g_bcp[j*LAT + n];
        float a0 = bc, a1 = bc, a2 = bc;
        for (int h = 0; h < HH; h++) {
            #pragma unroll 4
            for (int c = 0; c < DD; c++) {
                float wv = W_o[(h*256 + c)*LAT + n];
                a0 = fmaf(s_x1[(h*PP + 0)*DD + c], wv, a0);
                a1 = fmaf(s_x1[(h*PP + 1)*DD + c], wv, a1);
                a2 = fmaf(s_x1[(h*PP + 2)*DD + c], wv, a2);
            }
        }
        s_cf[0*LAT + n] = a0; s_cf[1*LAT + n] = a1; s_cf[2*LAT + n] = a2;
    }
    __syncthreads();
    for (int idx = tid; idx < 3*HID; idx += 256) {
        int k = idx / HID, j = idx % HID;
        float acc = (k == 0) ? b1[j] : 0.f;
        #pragma unroll 4
        for (int n = 0; n < LAT; n++)
            acc = fmaf(s_cf[k*LAT + n], W1[n*HID + j], acc);
        g_Dm[(b*3 + k)*HID + j] = acc;
    }
}

// ---------------- mma compute: one K=64 chunk ---------------------------
// browb = B smem row stride (bytes); bcol = byte offset of B k-window
__device__ __forceinline__ void mma_chunk64(
    float acc[2][8][4], uint32_t asb, uint32_t bsb,
    int m0w, int n0w, int lane, int browb, int bcol)
{
    #pragma unroll
    for (int ks = 0; ks < 4; ks++) {
        uint32_t a[2][4];
        #pragma unroll
        for (int mi = 0; mi < 2; mi++) {
            uint32_t ad = asb + (uint32_t)(m0w + mi*16 + (lane & 15)) * ROWB
                        + (uint32_t)(ks*32 + ((lane >> 4) << 4));
            LDM_X4(a[mi], ad);
        }
        uint32_t bfr[4][4];
        #pragma unroll
        for (int nt = 0; nt < 4; nt++) {
            int rown = n0w + nt*16 + ((lane >> 4) << 3) + (lane & 7);
            uint32_t bd = bsb + (uint32_t)rown * browb
                        + (uint32_t)(bcol + ks*32 + (((lane >> 3) & 1) << 4));
            LDM_X4(bfr[nt], bd);
        }
        #pragma unroll
        for (int mi = 0; mi < 2; mi++)
            #pragma unroll
            for (int nj = 0; nj < 8; nj++)
                MMA16816(acc[mi][nj], a[mi],
                         bfr[nj >> 1][(nj & 1)*2], bfr[nj >> 1][(nj & 1)*2 + 1]);
    }
}

// ---------------- K6: mma.sync W2 GEMM, K-chunk=64 ----------------------
// dyn smem: 0 s_t(512) | 512 s_b2(512) | 1024 s_D(6144) |
// 7168 A bufs 2x18432 | 44032 B bufs 2x18432 | total 80896
#define SM2_DYN 80896

__global__ void __launch_bounds__(256, 2)
k_mlp2m(const float* __restrict__ yts, const float* __restrict__ b2) {
    extern __shared__ char sm[];
    float* s_t  = (float*)(sm);
    float* s_b2 = (float*)(sm + 512);
    float* s_D  = (float*)(sm + 1024);

    int tid = threadIdx.x, lane = tid & 31, wid = tid >> 5;
    int m0 = blockIdx.x * 128;
    int n0 = blockIdx.y * 128;
    int b = m0 >> 10;
    int m0w = (wid & 3) * 32;
    int n0w = (wid >> 2) * 64;

    if (tid < 128) s_t[tid] = yts[b*TT + (m0 & 1023) + tid];
    for (int i = tid; i < 3*HID; i += 256) s_D[i] = g_Dm[b*3*HID + i];
    if (tid < 128) s_b2[tid] = b2[n0 + tid];
    __syncthreads();

    uint32_t sb = smem_u32(sm);
    uint32_t as0 = sb + 7168, as1 = sb + 7168 + 18432;
    uint32_t bs0 = sb + 44032, bs1 = sb + 44032 + 18432;

    int grow = tid >> 1;
    int gkh  = (tid & 1) << 5;          // 0/32 within 64-k chunk
    float t = s_t[grow];

    float acc[2][8][4];
    #pragma unroll
    for (int mi = 0; mi < 2; mi++)
        #pragma unroll
        for (int nj = 0; nj < 8; nj++)
            #pragma unroll
            for (int q = 0; q < 4; q++) acc[mi][nj][q] = 0.f;

    auto genA = [&](int kk, uint32_t asb) {
        int third = kk >> 3;                 // 8 chunks per 512
        int kloc = ((kk & 7) << 6) + gkh;    // within 512
        bool lo = (third == 1);
        uint32_t p[16];
        #pragma unroll
        for (int j2 = 0; j2 < 16; j2++) {
            float f[2];
            #pragma unroll
            for (int q = 0; q < 2; q++) {
                int k = kloc + j2*2 + q;
                float v = fmaf(t, fmaf(t, s_D[1024 + k], s_D[512 + k]), s_D[k]);
                v = fmaxf(v, 0.f);
                if (lo) v = v - __bfloat162float(__float2bfloat16_rn(v));
                f[q] = v;
            }
            p[j2] = pack2(f[0], f[1]);
        }
        uint32_t d = asb + (uint32_t)grow*ROWB + (uint32_t)(gkh << 1);
        asm volatile("st.shared.v4.b32 [%0], {%1,%2,%3,%4};"
                     :: "r"(d), "r"(p[0]), "r"(p[1]), "r"(p[2]), "r"(p[3]));
        asm volatile("st.shared.v4.b32 [%0+16], {%1,%2,%3,%4};"
                     :: "r"(d), "r"(p[4]), "r"(p[5]), "r"(p[6]), "r"(p[7]));
        asm volatile("st.shared.v4.b32 [%0+32], {%1,%2,%3,%4};"
                     :: "r"(d), "r"(p[8]), "r"(p[9]), "r"(p[10]), "r"(p[11]));
        asm volatile("st.shared.v4.b32 [%0+48], {%1,%2,%3,%4};"
                     :: "r"(d), "r"(p[12]), "r"(p[13]), "r"(p[14]), "r"(p[15]));
    };
    auto loadB = [&](int kk, uint32_t bsb) {
        #pragma unroll
        for (int i = 0; i < 4; i++) {
            int u = tid + (i << 8);
            int n = u >> 3, q = u & 7;
            uint32_t d = bsb + (uint32_t)n*ROWB + (uint32_t)(q << 4);
            const char* s = (const char*)g_B2
                + ((size_t)(n0 + n)*KP + (size_t)kk*64)*2 + q*16;
            CP16(d, s);
        }
    };

    genA(0, as0); loadB(0, bs0); CP_COMMIT();
    for (int kk = 0; kk < NKC2; kk++) {
        int buf = kk & 1;
        if (kk + 1 < NKC2) {
            genA(kk + 1, buf ? as0 : as1);
            loadB(kk + 1, buf ? bs0 : bs1);
            CP_COMMIT();
            CP_WAIT(1);
        } else {
            CP_WAIT(0);
        }
        __syncthreads();
        mma_chunk64(acc, buf ? as1 : as0, buf ? bs1 : bs0, m0w, n0w, lane, ROWB, 0);
        __syncthreads();
    }

    // ---- epilogue: relu+bias, split hi/lo, smem-staged coalesced stores ----
    char* stg = sm + 7168;                   // reuse A-buf region
    const int PADR = 136;
    #pragma unroll
    for (int round = 0; round < 2; round++) {
        #pragma unroll
        for (int mi = 0; mi < 2; mi++) {
            #pragma unroll
            for (int nj = 0; nj < 8; nj++) {
                int cl = n0w + nj*8 + (lane & 3)*2;
                #pragma unroll
                for (int half = 0; half < 2; half++) {
                    int r = m0w + mi*16 + (lane >> 2) + half*8;
                    float f0 = fmaxf(acc[mi][nj][half*2 + 0] + s_b2[cl], 0.f);
                    float f1 = fmaxf(acc[mi][nj][half*2 + 1] + s_b2[cl + 1], 0.f);
                    float h0 = __bfloat162float(__float2bfloat16_rn(f0));
                    float h1 = __bfloat162float(__float2bfloat16_rn(f1));
                    uint32_t v = (round == 0) ? pack2(h0, h1)
                                              : pack2(f0 - h0, f1 - h1);
                    *reinterpret_cast<uint32_t*>(stg + (r*PADR + cl)*2) = v;
                }
            }
        }
        __syncthreads();
        char* dstb = (round == 0) ? (char*)g_H2h : (char*)g_H2l;
        #pragma unroll
        for (int ps = 0; ps < 8; ps++) {
            int u = ps*256 + tid;
            int row = u >> 4, ch = u & 15;
            uint4 v = *reinterpret_cast<uint4*>(stg + row*PADR*2 + ch*16);
            *reinterpret_cast<uint4*>(dstb + ((size_t)(m0 + row)*HID + n0)*2 + ch*16) = v;
        }
        __syncthreads();
    }
}

// ---------------- K7: mma.sync W3 GEMM, A-reuse two-phase ---------------
// dyn smem: 0 s_b3(512) | 512 A bufs 2x18432 | 37376 B(wide) bufs 2x34816
// total 107008
#define SM3_DYN 107008

__global__ void __launch_bounds__(256, 2)
k_mlp3m(const float* __restrict__ b3, float* __restrict__ out) {
    extern __shared__ char sm[];
    float* s_b3 = (float*)(sm);

    int tid = threadIdx.x, lane = tid & 31, wid = tid >> 5;
    int m0 = blockIdx.x * 128;
    int m0w = (wid & 3) * 32;
    int n0w = (wid >> 2) * 64;

    if (tid < 128) s_b3[tid] = b3[tid];
    __syncthreads();

    uint32_t sb = smem_u32(sm);
    uint32_t as0 = sb + 512, as1 = sb + 512 + 18432;
    uint32_t bs0 = sb + 37376, bs1 = sb + 37376 + 34816;

    float acc[2][8][4];
    #pragma unroll
    for (int mi = 0; mi < 2; mi++)
        #pragma unroll
        for (int nj = 0; nj < 8; nj++)
            #pragma unroll
            for (int q = 0; q < 4; q++) acc[mi][nj][q] = 0.f;

    // iter i in [0,16): phase1 i<8 (A=H2h, B=[Bh|Bl] wide, 2 passes);
    // phase2 i>=8 (A=H2l, B=Bh only, 1 pass)
    auto loadA = [&](int i, uint32_t asb) {
        const char* asrc = (i < 8) ? (const char*)g_H2h : (const char*)g_H2l;
        int k0 = (i & 7) << 6;
        #pragma unroll
        for (int q2 = 0; q2 < 4; q2++) {
            int u = tid + (q2 << 8);
            int row = u >> 3, q = u & 7;
            uint32_t d = asb + (uint32_t)row*ROWB + (uint32_t)(q << 4);
            const char* s = asrc + ((size_t)(m0 + row)*HID + k0)*2 + q*16;
            CP16(d, s);
        }
    };
    auto loadB = [&](int i, uint32_t bsb) {
        int k0 = (i & 7) << 6;
        if (i < 8) {
            #pragma unroll
            for (int q2 = 0; q2 < 8; q2++) {
                int u = tid + (q2 << 8);
                int n = u >> 4, q = u & 15;
                uint32_t d = bsb + (uint32_t)n*ROWW + (uint32_t)(q << 4);
                const char* s = (q < 8)
                    ? (const char*)g_B3 + ((size_t)n*KP3 + k0)*2 + q*16
                    : (const char*)g_B3 + ((size_t)n*KP3 + 512 + k0)*2 + (q - 8)*16;
                CP16(d, s);
            }
        } else {
            #pragma unroll
            for (int q2 = 0; q2 < 4; q2++) {
                int u = tid + (q2 << 8);
                int n = u >> 3, q = u & 7;
                uint32_t d = bsb + (uint32_t)n*ROWW + (uint32_t)(q << 4);
                const char* s = (const char*)g_B3 + ((size_t)n*KP3 + k0)*2 + q*16;
                CP16(d, s);
            }
        }
    };

    loadA(0, as0); loadB(0, bs0); CP_COMMIT();
    for (int i = 0; i < 16; i++) {
        int buf = i & 1;
        if (i + 1 < 16) {
            loadA(i + 1, buf ? as0 : as1);
            loadB(i + 1, buf ? bs0 : bs1);
            CP_COMMIT();
            CP_WAIT(1);
        } else {
            CP_WAIT(0);
        }
        __syncthreads();
        uint32_t aa = buf ? as1 : as0, bb = buf ? bs1 : bs0;
        mma_chunk64(acc, aa, bb, m0w, n0w, lane, ROWW, 0);
        if (i < 8)
            mma_chunk64(acc, aa, bb, m0w, n0w, lane, ROWW, 128);
        __syncthreads();
    }

    #pragma unroll
    for (int mi = 0; mi < 2; mi++) {
        #pragma unroll
        for (int nj = 0; nj < 8; nj++) {
            int cl = n0w + nj*8 + (lane & 3)*2;
            int rg = m0 + m0w + mi*16 + (lane >> 2);
            #pragma unroll
            for (int half = 0; half < 2; half++) {
                int r = rg + half*8;
                float2 v;
                v.x = acc[mi][nj][half*2 + 0] + s_b3[cl];
                v.y = acc[mi][nj][half*2 + 1] + s_b3[cl + 1];
                *reinterpret_cast<float2*>(&out[(size_t)r*DD + cl]) = v;
            }
        }
    }
}

// ---------------- launch -------------------------------------------------
extern "C" void kernel_launch(void* const* d_in, const int* in_sizes, int n_in,
                              void* d_out, int out_size) {
    const float* timesteps = (const float*)d_in[0];
    const float* X         = (const float*)d_in[1];
    const float* M         = (const float*)d_in[2];
    const float* yts       = (const float*)d_in[3];
    const float* w_te      = (const float*)d_in[4];
    const float* b_te      = (const float*)d_in[5];
    const float* query     = (const float*)d_in[6];
    const float* W_q       = (const float*)d_in[7];
    const float* b_q       = (const float*)d_in[8];
    const float* W_k       = (const float*)d_in[9];
    const float* b_k       = (const float*)d_in[10];
    const float* W_o       = (const float*)d_in[11];
    const float* b_o       = (const float*)d_in[12];
    const float* W1        = (const float*)d_in[13];
    const float* b1        = (const float*)d_in[14];
    const float* W2        = (const float*)d_in[15];
    const float* b2        = (const float*)d_in[16];
    const float* W3        = (const float*)d_in[17];
    const float* b3        = (const float*)d_in[18];
    float* out = (float*)d_out;

    cudaFuncSetAttribute(k_mlp2m, cudaFuncAttributeMaxDynamicSharedMemorySize, SM2_DYN);
    cudaFuncSetAttribute(k_mlp3m, cudaFuncAttributeMaxDynamicSharedMemorySize, SM3_DYN);

    k_setup_q<<<6, 256>>>(query, W_q, b_q);
    k_prepW<<<80, 256>>>(W2, W3);
    k_bcpart<<<8, 256>>>(W_o);
    k_setup_A<<<48, 256>>>(W_k);
    k_setup_misc<<<2, 256>>>(b_k, w_te, b_te);
    k_scores<<<BB*LL/256, 256>>>(timesteps);
    k_att_partial<<<SPL*BB, 256>>>(X, M);
    k_coeffs<<<BB, 256>>>(W_o, W1, b1, b_o);
    k_mlp2m<<<dim3(BB*TT/128, 4), 256, SM2_DYN>>>(yts, b2);
    k_mlp3m<<<BB*TT/128, 256, SM3_DYN>>>(b3, out);
}

// round 10
// speedup vs baseline: 2.3782x; 1.1636x over previous
#include <cuda_runtime.h>
#include <cuda_bf16.h>
#include <cuda_fp16.h>
#include <math.h>
#include <stdint.h>

#define BB 64
#define LL 2048
#define TT 1024
#define DD 128
#define EE 512
#define HH 8
#define PP 3
#define HP 24
#define LAT 256
#define HID 512
#define NSIN 64
#define SPL 8
#define LSP (LL/SPL)
#define NKC2 16          // mlp2: K'=1024 in chunks of 64
#define NKC3 16          // mlp3: K'=1024 in chunks of 64
#define ROWB 144         // A/B smem row bytes (64 fp16 + 8 pad)

// ---------------- static device scratch (no allocations) ----------------
__device__ float g_q[PP*EE];
__device__ float g_A[EE*HP];
__device__ float g_lin[HP];
__device__ float g_off[HP];
__device__ float g_ws[NSIN];
__device__ float g_bs[NSIN];
__device__ float g_Asin[NSIN*HP];
__device__ float g_bcp[8*LAT];
__device__ float g_scores[BB*LL*HP];
__device__ unsigned int g_maxu[BB*HP];
__device__ float g_part[SPL*BB*HP*256];
__device__ float g_Dm[BB*3*HID];
__device__ __align__(16) __half g_B2[512*512];               // W2 fp16, [n][k]
__device__ __align__(16) __half g_B3[128*512];               // W3 fp16, [n][k]
__device__ __align__(16) __half g_H2h[(size_t)BB*TT*HID];
__device__ __align__(16) __half g_H2l[(size_t)BB*TT*HID];

__device__ __forceinline__ unsigned int enc_f(float f) {
    unsigned int u = __float_as_uint(f);
    return (u & 0x80000000u) ? ~u : (u | 0x80000000u);
}
__device__ __forceinline__ float dec_f(unsigned int u) {
    return (u & 0x80000000u) ? __uint_as_float(u & 0x7FFFFFFFu)
                             : __uint_as_float(~u);
}

// ---------------- PTX helpers -------------------------------------------
__device__ __forceinline__ uint32_t smem_u32(const void* p) {
    uint32_t a;
    asm("{ .reg .u64 t; cvta.to.shared.u64 t, %1; cvt.u32.u64 %0, t; }"
        : "=r"(a) : "l"(p));
    return a;
}
__device__ __forceinline__ uint32_t pack2h(float a, float b) {
    __half2 h = __floats2half2_rn(a, b);
    return *reinterpret_cast<uint32_t*>(&h);
}

#define CP16(dst, src) \
    asm volatile("cp.async.cg.shared.global [%0], [%1], 16;" :: "r"(dst), "l"(src))
#define CP_COMMIT() asm volatile("cp.async.commit_group;" ::: "memory")
#define CP_WAIT(n)  asm volatile("cp.async.wait_group %0;" :: "n"(n) : "memory")

#define LDM_X4(r, addr) \
    asm volatile("ldmatrix.sync.aligned.m8n8.x4.shared.b16 {%0,%1,%2,%3}, [%4];" \
        : "=r"((r)[0]), "=r"((r)[1]), "=r"((r)[2]), "=r"((r)[3]) : "r"(addr))

#define MMA16816(c, a, b0, b1) \
    asm volatile("mma.sync.aligned.m16n8k16.row.col.f32.f16.f16.f32 " \
        "{%0,%1,%2,%3}, {%4,%5,%6,%7}, {%8,%9}, {%0,%1,%2,%3};" \
        : "+f"((c)[0]), "+f"((c)[1]), "+f"((c)[2]), "+f"((c)[3]) \
        : "r"((a)[0]), "r"((a)[1]), "r"((a)[2]), "r"((a)[3]), "r"(b0), "r"(b1))

// ---------------- setup kernels -----------------------------------------
__global__ void k_setup_q(const float* __restrict__ query,
                          const float* __restrict__ W_q,
                          const float* __restrict__ b_q) {
    int idx = blockIdx.x * 256 + threadIdx.x;   // < 1536
    int p = idx / EE, e = idx % EE;
    float acc = b_q[e];
    for (int i = 0; i < EE; i++)
        acc = fmaf(query[p*EE + i], W_q[i*EE + e], acc);
    g_q[idx] = acc;
}

__global__ void k_setup_A(const float* __restrict__ W_k) {
    int idx = blockIdx.x * 256 + threadIdx.x;   // < 12288
    int e = idx / HP, hp = idx % HP;
    int h = hp / PP, p = hp % PP;
    float acc = 0.f;
    #pragma unroll 4
    for (int j = 0; j < 64; j++)
        acc = fmaf(W_k[e*EE + h*64 + j], g_q[p*EE + h*64 + j], acc);
    g_A[idx] = acc * 0.125f;
}

__global__ void k_setup_misc(const float* __restrict__ b_k,
                             const float* __restrict__ w_te,
                             const float* __restrict__ b_te) {
    int tid = threadIdx.x;
    int bid = blockIdx.x;
    if (bid == 0) {
        if (tid < HP) {
            int hp = tid, h = hp / PP, p = hp % PP;
            float lin = 0.f, off = 0.f;
            for (int j = 0; j < 64; j++)
                off = fmaf(g_q[p*EE + h*64 + j], b_k[h*64 + j], off);
            off *= 0.125f;
            for (int e = 0; e < EE; e++) {
                if ((e & 7) != 0) {
                    float a = g_A[e*HP + hp];
                    lin = fmaf(w_te[e], a, lin);
                    off = fmaf(b_te[e], a, off);
                }
            }
            g_lin[hp] = lin; g_off[hp] = off;
        }
        if (tid < NSIN) { g_ws[tid] = w_te[8*tid]; g_bs[tid] = b_te[8*tid]; }
    } else {
        for (int idx = tid; idx < NSIN*HP; idx += 256) {
            int j = idx / HP, hp = idx % HP;
            g_Asin[idx] = g_A[(8*j)*HP + hp];
        }
        for (int i = tid; i < BB*HP; i += 256) g_maxu[i] = 0u;
    }
}

// ---------------- bconst partials ---------------------------------------
__global__ void k_bcpart(const float* __restrict__ W_o) {
    int h = blockIdx.x;           // 0..7
    int n = threadIdx.x;          // 0..255
    float acc = 0.f;
    const float* base = W_o + (size_t)(h*256 + 128)*LAT + n;
    #pragma unroll 8
    for (int c = 0; c < DD; c++)
        acc += base[(size_t)c*LAT];
    g_bcp[h*LAT + n] = acc;
}

// ---------------- W2/W3 fp16 prep (smem-tiled transpose) ----------------
__global__ void k_prepW(const float* __restrict__ W2,
                        const float* __restrict__ W3) {
    __shared__ float s_tile[64][65];
    int bid = blockIdx.x;         // 0..79
    int tid = threadIdx.x;
    int c = tid & 63, rloc = tid >> 6;

    const float* src;
    int tk, tn, src_cols;
    bool isW2 = (bid < 64);
    if (isW2) { tk = bid >> 3; tn = bid & 7; src = W2; src_cols = 512; }
    else      { int l = bid - 64; tk = l >> 1; tn = l & 1; src = W3; src_cols = 128; }

    #pragma unroll
    for (int i = 0; i < 16; i++) {
        int row = rloc + i*4;
        s_tile[row][c] = src[(size_t)(tk*64 + row)*src_cols + tn*64 + c];
    }
    __syncthreads();
    #pragma unroll
    for (int i = 0; i < 16; i++) {
        int n = rloc + i*4;
        __half h = __float2half_rn(s_tile[c][n]);
        if (isW2) g_B2[(size_t)(tn*64 + n)*512 + tk*64 + c] = h;
        else      g_B3[(size_t)(tn*64 + n)*512 + tk*64 + c] = h;
    }
}

// ---------------- K2: scores + per-(b,hp) max ---------------------------
__global__ void k_scores(const float* __restrict__ timesteps) {
    __shared__ float s_Asin[NSIN*HP];
    __shared__ float s_lin[HP], s_off[HP];
    __shared__ float s_ws[NSIN], s_bs[NSIN];
    __shared__ unsigned int s_max[HP];
    int tid = threadIdx.x;
    int g = blockIdx.x * 256 + tid;
    int b = g / LL;
    for (int i = tid; i < NSIN*HP; i += 256) s_Asin[i] = g_Asin[i];
    if (tid < HP) { s_lin[tid] = g_lin[tid]; s_off[tid] = g_off[tid]; s_max[tid] = 0u; }
    if (tid < NSIN) { s_ws[tid] = g_ws[tid]; s_bs[tid] = g_bs[tid]; }
    __syncthreads();

    float t = timesteps[g];
    float acc[HP];
    #pragma unroll
    for (int hp = 0; hp < HP; hp++) acc[hp] = fmaf(t, s_lin[hp], s_off[hp]);
    for (int j = 0; j < NSIN; j++) {
        float s = __sinf(fmaf(t, s_ws[j], s_bs[j]));
        #pragma unroll
        for (int hp = 0; hp < HP; hp++)
            acc[hp] = fmaf(s, s_Asin[j*HP + hp], acc[hp]);
    }
    #pragma unroll
    for (int hp = 0; hp < HP; hp++) {
        g_scores[g*HP + hp] = acc[hp];
        atomicMax(&s_max[hp], enc_f(acc[hp]));
    }
    __syncthreads();
    if (tid < HP) atomicMax(&g_maxu[b*HP + tid], s_max[tid]);
}

// ---------------- K3: attention partial sums ----------------------------
__global__ void k_att_partial(const float* __restrict__ X,
                              const float* __restrict__ M) {
    __shared__ float s_m[HP];
    __shared__ float s_w[64*HP];
    int tid = threadIdx.x;
    int b  = blockIdx.x / SPL;
    int sp = blockIdx.x % SPL;
    int l0 = sp * LSP;
    if (tid < HP) s_m[tid] = dec_f(g_maxu[b*HP + tid]);
    float acc[HP];
    #pragma unroll
    for (int hp = 0; hp < HP; hp++) acc[hp] = 0.f;
    int c = tid;

    for (int ch = 0; ch < LSP; ch += 64) {
        __syncthreads();
        for (int i = tid; i < 64*HP; i += 256) {
            int li = i / HP, hp = i % HP;
            float sc = g_scores[(b*LL + l0 + ch + li)*HP + hp];
            s_w[i] = __expf(sc - s_m[hp]);
        }
        __syncthreads();
        for (int li = 0; li < 64; li++) {
            int l = l0 + ch + li;
            float f;
            if (c < DD) {
                float xv = X[((long)b*LL + l)*DD + c];
                float mv = M[((long)b*LL + l)*DD + c];
                f = xv * mv;
            } else {
                f = M[((long)b*LL + l)*DD + (c - DD)];
            }
            #pragma unroll
            for (int hp = 0; hp < HP; hp++)
                acc[hp] = fmaf(s_w[li*HP + hp], f, acc[hp]);
        }
    }
    for (int hp = 0; hp < HP; hp++)
        g_part[(((sp*BB) + b)*HP + hp)*256 + c] = acc[hp];
}

// ---------------- K5: x1 (fused reduce), coeffs, D-matrices -------------
__global__ void k_coeffs(const float* __restrict__ W_o,
                         const float* __restrict__ W1,
                         const float* __restrict__ b1,
                         const float* __restrict__ b_o) {
    __shared__ float s_x1[HP*DD];
    __shared__ float s_cf[PP*LAT];
    int tid = threadIdx.x;
    int b = blockIdx.x;
    for (int i = tid; i < HP*DD; i += 256) {
        int hp = i / DD, c = i % DD;
        float num = 0.f, den = 0.f;
        #pragma unroll
        for (int sp = 0; sp < SPL; sp++) {
            int base = (((sp*BB) + b)*HP + hp)*256;
            num += g_part[base + c];
            den += g_part[base + 128 + c];
        }
        s_x1[i] = num / den;
    }
    __syncthreads();
    {
        int n = tid;
        float bc = b_o[n];
        #pragma unroll
        for (int j = 0; j < 8; j++) bc += g_bcp[j*LAT + n];
        float a0 = bc, a1 = bc, a2 = bc;
        for (int h = 0; h < HH; h++) {
            #pragma unroll 4
            for (int c = 0; c < DD; c++) {
                float wv = W_o[(h*256 + c)*LAT + n];
                a0 = fmaf(s_x1[(h*PP + 0)*DD + c], wv, a0);
                a1 = fmaf(s_x1[(h*PP + 1)*DD + c], wv, a1);
                a2 = fmaf(s_x1[(h*PP + 2)*DD + c], wv, a2);
            }
        }
        s_cf[0*LAT + n] = a0; s_cf[1*LAT + n] = a1; s_cf[2*LAT + n] = a2;
    }
    __syncthreads();
    for (int idx = tid; idx < 3*HID; idx += 256) {
        int k = idx / HID, j = idx % HID;
        float acc = (k == 0) ? b1[j] : 0.f;
        #pragma unroll 4
        for (int n = 0; n < LAT; n++)
            acc = fmaf(s_cf[k*LAT + n], W1[n*HID + j], acc);
        g_Dm[(b*3 + k)*HID + j] = acc;
    }
}

// ---------------- mma compute: one K=64 chunk ---------------------------
__device__ __forceinline__ void mma_chunk64(
    float acc[2][8][4], uint32_t asb, uint32_t bsb,
    int m0w, int n0w, int lane)
{
    #pragma unroll
    for (int ks = 0; ks < 4; ks++) {
        uint32_t a[2][4];
        #pragma unroll
        for (int mi = 0; mi < 2; mi++) {
            uint32_t ad = asb + (uint32_t)(m0w + mi*16 + (lane & 15)) * ROWB
                        + (uint32_t)(ks*32 + ((lane >> 4) << 4));
            LDM_X4(a[mi], ad);
        }
        uint32_t bfr[4][4];
        #pragma unroll
        for (int nt = 0; nt < 4; nt++) {
            int rown = n0w + nt*16 + ((lane >> 4) << 3) + (lane & 7);
            uint32_t bd = bsb + (uint32_t)rown * ROWB
                        + (uint32_t)(ks*32 + (((lane >> 3) & 1) << 4));
            LDM_X4(bfr[nt], bd);
        }
        #pragma unroll
        for (int mi = 0; mi < 2; mi++)
            #pragma unroll
            for (int nj = 0; nj < 8; nj++)
                MMA16816(acc[mi][nj], a[mi],
                         bfr[nj >> 1][(nj & 1)*2], bfr[nj >> 1][(nj & 1)*2 + 1]);
    }
}

// ---------------- K6: W2 GEMM, fp16 2-term split, K'=1024 ---------------
// dyn smem: 0 s_t(512) | 512 s_b2(512) | 1024 s_D(6144) |
// 7168 A bufs 2x18432 | 44032 B bufs 2x18432 | total 80896
#define SM2_DYN 80896

__global__ void __launch_bounds__(256, 2)
k_mlp2m(const float* __restrict__ yts, const float* __restrict__ b2) {
    extern __shared__ char sm[];
    float* s_t  = (float*)(sm);
    float* s_b2 = (float*)(sm + 512);
    float* s_D  = (float*)(sm + 1024);

    int tid = threadIdx.x, lane = tid & 31, wid = tid >> 5;
    int m0 = blockIdx.x * 128;
    int n0 = blockIdx.y * 128;
    int b = m0 >> 10;
    int m0w = (wid & 3) * 32;
    int n0w = (wid >> 2) * 64;

    if (tid < 128) s_t[tid] = yts[b*TT + (m0 & 1023) + tid];
    for (int i = tid; i < 3*HID; i += 256) s_D[i] = g_Dm[b*3*HID + i];
    if (tid < 128) s_b2[tid] = b2[n0 + tid];
    __syncthreads();

    uint32_t sb = smem_u32(sm);
    uint32_t as0 = sb + 7168, as1 = sb + 7168 + 18432;
    uint32_t bs0 = sb + 44032, bs1 = sb + 44032 + 18432;

    int grow = tid >> 1;
    int gkh  = (tid & 1) << 5;          // 0/32 within 64-k chunk
    float t = s_t[grow];

    float acc[2][8][4];
    #pragma unroll
    for (int mi = 0; mi < 2; mi++)
        #pragma unroll
        for (int nj = 0; nj < 8; nj++)
            #pragma unroll
            for (int q = 0; q < 4; q++) acc[mi][nj][q] = 0.f;

    // A' = [h1_hi (kk<8) | h1_lo (kk>=8)], fp16 exact split
    auto genA = [&](int kk, uint32_t asb) {
        bool lo = (kk >= 8);
        int kloc = ((kk & 7) << 6) + gkh;
        uint32_t p[16];
        #pragma unroll
        for (int j2 = 0; j2 < 16; j2++) {
            float f[2];
            #pragma unroll
            for (int q = 0; q < 2; q++) {
                int k = kloc + j2*2 + q;
                float v = fmaf(t, fmaf(t, s_D[1024 + k], s_D[512 + k]), s_D[k]);
                v = fmaxf(v, 0.f);
                if (lo) v = v - __half2float(__float2half_rn(v));
                f[q] = v;
            }
            p[j2] = pack2h(f[0], f[1]);
        }
        uint32_t d = asb + (uint32_t)grow*ROWB + (uint32_t)(gkh << 1);
        asm volatile("st.shared.v4.b32 [%0], {%1,%2,%3,%4};"
                     :: "r"(d), "r"(p[0]), "r"(p[1]), "r"(p[2]), "r"(p[3]));
        asm volatile("st.shared.v4.b32 [%0+16], {%1,%2,%3,%4};"
                     :: "r"(d), "r"(p[4]), "r"(p[5]), "r"(p[6]), "r"(p[7]));
        asm volatile("st.shared.v4.b32 [%0+32], {%1,%2,%3,%4};"
                     :: "r"(d), "r"(p[8]), "r"(p[9]), "r"(p[10]), "r"(p[11]));
        asm volatile("st.shared.v4.b32 [%0+48], {%1,%2,%3,%4};"
                     :: "r"(d), "r"(p[12]), "r"(p[13]), "r"(p[14]), "r"(p[15]));
    };
    // B window repeats mod 512 (kk and kk+8 read the same W2 cols)
    auto loadB = [&](int kk, uint32_t bsb) {
        #pragma unroll
        for (int i = 0; i < 4; i++) {
            int u = tid + (i << 8);
            int n = u >> 3, q = u & 7;
            uint32_t d = bsb + (uint32_t)n*ROWB + (uint32_t)(q << 4);
            const char* s = (const char*)g_B2
                + ((size_t)(n0 + n)*512 + (size_t)(kk & 7)*64)*2 + q*16;
            CP16(d, s);
        }
    };

    genA(0, as0); loadB(0, bs0); CP_COMMIT();
    for (int kk = 0; kk < NKC2; kk++) {
        int buf = kk & 1;
        if (kk + 1 < NKC2) {
            genA(kk + 1, buf ? as0 : as1);
            loadB(kk + 1, buf ? bs0 : bs1);
            CP_COMMIT();
            CP_WAIT(1);
        } else {
            CP_WAIT(0);
        }
        __syncthreads();
        mma_chunk64(acc, buf ? as1 : as0, buf ? bs1 : bs0, m0w, n0w, lane);
        __syncthreads();
    }

    // ---- epilogue: relu+bias, fp16 hi/lo split, smem-staged stores ----
    char* stg = sm + 7168;                   // reuse A-buf region
    const int PADR = 136;
    #pragma unroll
    for (int round = 0; round < 2; round++) {
        #pragma unroll
        for (int mi = 0; mi < 2; mi++) {
            #pragma unroll
            for (int nj = 0; nj < 8; nj++) {
                int cl = n0w + nj*8 + (lane & 3)*2;
                #pragma unroll
                for (int half = 0; half < 2; half++) {
                    int r = m0w + mi*16 + (lane >> 2) + half*8;
                    float f0 = fmaxf(acc[mi][nj][half*2 + 0] + s_b2[cl], 0.f);
                    float f1 = fmaxf(acc[mi][nj][half*2 + 1] + s_b2[cl + 1], 0.f);
                    float h0 = __half2float(__float2half_rn(f0));
                    float h1 = __half2float(__float2half_rn(f1));
                    uint32_t v = (round == 0) ? pack2h(h0, h1)
                                              : pack2h(f0 - h0, f1 - h1);
                    *reinterpret_cast<uint32_t*>(stg + (r*PADR + cl)*2) = v;
                }
            }
        }
        __syncthreads();
        char* dstb = (round == 0) ? (char*)g_H2h : (char*)g_H2l;
        #pragma unroll
        for (int ps = 0; ps < 8; ps++) {
            int u = ps*256 + tid;
            int row = u >> 4, ch = u & 15;
            uint4 v = *reinterpret_cast<uint4*>(stg + row*PADR*2 + ch*16);
            *reinterpret_cast<uint4*>(dstb + ((size_t)(m0 + row)*HID + n0)*2 + ch*16) = v;
        }
        __syncthreads();
    }
}

// ---------------- K7: W3 GEMM, fp16 2-term split, K'=1024 ---------------
// dyn smem: 0 s_b3(512) | 512 A bufs 2x18432 | 37376 B bufs 2x18432
// total 74240
#define SM3_DYN 74240

__global__ void __launch_bounds__(256, 2)
k_mlp3m(const float* __restrict__ b3, float* __restrict__ out) {
    extern __shared__ char sm[];
    float* s_b3 = (float*)(sm);

    int tid = threadIdx.x, lane = tid & 31, wid = tid >> 5;
    int m0 = blockIdx.x * 128;
    int m0w = (wid & 3) * 32;
    int n0w = (wid >> 2) * 64;

    if (tid < 128) s_b3[tid] = b3[tid];
    __syncthreads();

    uint32_t sb = smem_u32(sm);
    uint32_t as0 = sb + 512, as1 = sb + 512 + 18432;
    uint32_t bs0 = sb + 37376, bs1 = sb + 37376 + 18432;

    float acc[2][8][4];
    #pragma unroll
    for (int mi = 0; mi < 2; mi++)
        #pragma unroll
        for (int nj = 0; nj < 8; nj++)
            #pragma unroll
            for (int q = 0; q < 4; q++) acc[mi][nj][q] = 0.f;

    // A' = [H2h (i<8) | H2l (i>=8)]; B window = (i&7)*64
    auto loadA = [&](int i, uint32_t asb) {
        const char* asrc = (i < 8) ? (const char*)g_H2h : (const char*)g_H2l;
        int k0 = (i & 7) << 6;
        #pragma unroll
        for (int q2 = 0; q2 < 4; q2++) {
            int u = tid + (q2 << 8);
            int row = u >> 3, q = u & 7;
            uint32_t d = asb + (uint32_t)row*ROWB + (uint32_t)(q << 4);
            const char* s = asrc + ((size_t)(m0 + row)*HID + k0)*2 + q*16;
            CP16(d, s);
        }
    };
    auto loadB = [&](int i, uint32_t bsb) {
        int k0 = (i & 7) << 6;
        #pragma unroll
        for (int q2 = 0; q2 < 4; q2++) {
            int u = tid + (q2 << 8);
            int n = u >> 3, q = u & 7;
            uint32_t d = bsb + (uint32_t)n*ROWB + (uint32_t)(q << 4);
            const char* s = (const char*)g_B3 + ((size_t)n*512 + k0)*2 + q*16;
            CP16(d, s);
        }
    };

    loadA(0, as0); loadB(0, bs0); CP_COMMIT();
    for (int i = 0; i < NKC3; i++) {
        int buf = i & 1;
        if (i + 1 < NKC3) {
            loadA(i + 1, buf ? as0 : as1);
            loadB(i + 1, buf ? bs0 : bs1);
            CP_COMMIT();
            CP_WAIT(1);
        } else {
            CP_WAIT(0);
        }
        __syncthreads();
        mma_chunk64(acc, buf ? as1 : as0, buf ? bs1 : bs0, m0w, n0w, lane);
        __syncthreads();
    }

    #pragma unroll
    for (int mi = 0; mi < 2; mi++) {
        #pragma unroll
        for (int nj = 0; nj < 8; nj++) {
            int cl = n0w + nj*8 + (lane & 3)*2;
            int rg = m0 + m0w + mi*16 + (lane >> 2);
            #pragma unroll
            for (int half = 0; half < 2; half++) {
                int r = rg + half*8;
                float2 v;
                v.x = acc[mi][nj][half*2 + 0] + s_b3[cl];
                v.y = acc[mi][nj][half*2 + 1] + s_b3[cl + 1];
                *reinterpret_cast<float2*>(&out[(size_t)r*DD + cl]) = v;
            }
        }
    }
}

// ---------------- launch -------------------------------------------------
extern "C" void kernel_launch(void* const* d_in, const int* in_sizes, int n_in,
                              void* d_out, int out_size) {
    const float* timesteps = (const float*)d_in[0];
    const float* X         = (const float*)d_in[1];
    const float* M         = (const float*)d_in[2];
    const float* yts       = (const float*)d_in[3];
    const float* w_te      = (const float*)d_in[4];
    const float* b_te      = (const float*)d_in[5];
    const float* query     = (const float*)d_in[6];
    const float* W_q       = (const float*)d_in[7];
    const float* b_q       = (const float*)d_in[8];
    const float* W_k       = (const float*)d_in[9];
    const float* b_k       = (const float*)d_in[10];
    const float* W_o       = (const float*)d_in[11];
    const float* b_o       = (const float*)d_in[12];
    const float* W1        = (const float*)d_in[13];
    const float* b1        = (const float*)d_in[14];
    const float* W2        = (const float*)d_in[15];
    const float* b2        = (const float*)d_in[16];
    const float* W3        = (const float*)d_in[17];
    const float* b3        = (const float*)d_in[18];
    float* out = (float*)d_out;

    cudaFuncSetAttribute(k_mlp2m, cudaFuncAttributeMaxDynamicSharedMemorySize, SM2_DYN);
    cudaFuncSetAttribute(k_mlp3m, cudaFuncAttributeMaxDynamicSharedMemorySize, SM3_DYN);

    k_setup_q<<<6, 256>>>(query, W_q, b_q);
    k_prepW<<<80, 256>>>(W2, W3);
    k_bcpart<<<8, 256>>>(W_o);
    k_setup_A<<<48, 256>>>(W_k);
    k_setup_misc<<<2, 256>>>(b_k, w_te, b_te);
    k_scores<<<BB*LL/256, 256>>>(timesteps);
    k_att_partial<<<SPL*BB, 256>>>(X, M);
    k_coeffs<<<BB, 256>>>(W_o, W1, b1, b_o);
    k_mlp2m<<<dim3(BB*TT/128, 4), 256, SM2_DYN>>>(yts, b2);
    k_mlp3m<<<BB*TT/128, 256, SM3_DYN>>>(b3, out);
}

// round 11
// speedup vs baseline: 2.9658x; 1.2470x over previous
#include <cuda_runtime.h>
#include <cuda_fp16.h>
#include <math.h>
#include <stdint.h>

#define BB 64
#define LL 2048
#define TT 1024
#define DD 128
#define EE 512
#define HH 8
#define PP 3
#define HP 24
#define LAT 256
#define HID 512
#define NSIN 64
#define SPL 8
#define LSP (LL/SPL)
#define NKC2 8           // mlp2: K=512 in chunks of 64
#define NKC3 8           // mlp3: K=512 in chunks of 64
#define ROWB 144         // A/B smem row bytes (64 fp16 + 8 pad)

// ---------------- static device scratch (no allocations) ----------------
__device__ float g_q[PP*EE];
__device__ float g_A[EE*HP];
__device__ float g_lin[HP];
__device__ float g_off[HP];
__device__ float g_bound[HP];
__device__ float g_ws[NSIN];
__device__ float g_bs[NSIN];
__device__ float g_Asin[NSIN*HP];
__device__ float g_bcp[8*LAT];
__device__ float g_scores[BB*LL*HP];
__device__ float g_part[SPL*BB*HP*256];
__device__ float g_Dm[BB*3*HID];
__device__ __align__(16) __half g_B2[512*512];               // W2 fp16, [n][k]
__device__ __align__(16) __half g_B3[128*512];               // W3 fp16, [n][k]
__device__ __align__(16) __half g_H2[(size_t)BB*TT*HID];     // relu(h1@W2+b2) fp16

// ---------------- PTX helpers -------------------------------------------
__device__ __forceinline__ uint32_t smem_u32(const void* p) {
    uint32_t a;
    asm("{ .reg .u64 t; cvta.to.shared.u64 t, %1; cvt.u32.u64 %0, t; }"
        : "=r"(a) : "l"(p));
    return a;
}
__device__ __forceinline__ uint32_t pack2h(float a, float b) {
    __half2 h = __floats2half2_rn(a, b);
    return *reinterpret_cast<uint32_t*>(&h);
}
// sin via pi-reduction + deg-11 odd Taylor; |err| < 1e-7 for |x| < ~6
__device__ __forceinline__ float sin_poly(float x) {
    float xn = rintf(x * 0.31830988618f);
    float xr = fmaf(xn, -3.14159274f, x);
    xr = fmaf(xn, 8.742278e-8f, xr);
    float x2 = xr * xr;
    float p = -2.50521084e-8f;
    p = fmaf(p, x2, 2.75573192e-6f);
    p = fmaf(p, x2, -1.98412698e-4f);
    p = fmaf(p, x2, 8.33333333e-3f);
    p = fmaf(p, x2, -1.66666667e-1f);
    float s = xr * fmaf(p, x2, 1.0f);
    int ni = (int)xn;
    return __int_as_float(__float_as_int(s) ^ ((ni & 1) << 31));
}

#define CP16(dst, src) \
    asm volatile("cp.async.cg.shared.global [%0], [%1], 16;" :: "r"(dst), "l"(src))
#define CP_COMMIT() asm volatile("cp.async.commit_group;" ::: "memory")
#define CP_WAIT(n)  asm volatile("cp.async.wait_group %0;" :: "n"(n) : "memory")

#define LDM_X4(r, addr) \
    asm volatile("ldmatrix.sync.aligned.m8n8.x4.shared.b16 {%0,%1,%2,%3}, [%4];" \
        : "=r"((r)[0]), "=r"((r)[1]), "=r"((r)[2]), "=r"((r)[3]) : "r"(addr))

#define MMA16816(c, a, b0, b1) \
    asm volatile("mma.sync.aligned.m16n8k16.row.col.f32.f16.f16.f32 " \
        "{%0,%1,%2,%3}, {%4,%5,%6,%7}, {%8,%9}, {%0,%1,%2,%3};" \
        : "+f"((c)[0]), "+f"((c)[1]), "+f"((c)[2]), "+f"((c)[3]) \
        : "r"((a)[0]), "r"((a)[1]), "r"((a)[2]), "r"((a)[3]), "r"(b0), "r"(b1))

// ---------------- setup kernels -----------------------------------------
__global__ void k_setup_q(const float* __restrict__ query,
                          const float* __restrict__ W_q,
                          const float* __restrict__ b_q) {
    int idx = blockIdx.x * 256 + threadIdx.x;   // < 1536
    int p = idx / EE, e = idx % EE;
    float acc = b_q[e];
    for (int i = 0; i < EE; i++)
        acc = fmaf(query[p*EE + i], W_q[i*EE + e], acc);
    g_q[idx] = acc;
}

__global__ void k_setup_A(const float* __restrict__ W_k) {
    int idx = blockIdx.x * 256 + threadIdx.x;   // < 12288
    int e = idx / HP, hp = idx % HP;
    int h = hp / PP, p = hp % PP;
    float acc = 0.f;
    #pragma unroll 4
    for (int j = 0; j < 64; j++)
        acc = fmaf(W_k[e*EE + h*64 + j], g_q[p*EE + h*64 + j], acc);
    g_A[idx] = acc * 0.125f;
}

__global__ void k_setup_misc(const float* __restrict__ b_k,
                             const float* __restrict__ w_te,
                             const float* __restrict__ b_te) {
    int tid = threadIdx.x;
    int bid = blockIdx.x;
    if (bid == 0) {
        if (tid < HP) {
            int hp = tid, h = hp / PP, p = hp % PP;
            float lin = 0.f, off = 0.f;
            for (int j = 0; j < 64; j++)
                off = fmaf(g_q[p*EE + h*64 + j], b_k[h*64 + j], off);
            off *= 0.125f;
            for (int e = 0; e < EE; e++) {
                if ((e & 7) != 0) {
                    float a = g_A[e*HP + hp];
                    lin = fmaf(w_te[e], a, lin);
                    off = fmaf(b_te[e], a, off);
                }
            }
            g_lin[hp] = lin; g_off[hp] = off;
            // upper bound on scores over t in [0,1): off + max(lin,0) + sum|Asin|
            float bnd = off + fmaxf(lin, 0.f);
            for (int j = 0; j < NSIN; j++)
                bnd += fabsf(g_A[(8*j)*HP + hp]);
            g_bound[hp] = bnd;
        }
        if (tid < NSIN) { g_ws[tid] = w_te[8*tid]; g_bs[tid] = b_te[8*tid]; }
    } else {
        for (int idx = tid; idx < NSIN*HP; idx += 256) {
            int j = idx / HP, hp = idx % HP;
            g_Asin[idx] = g_A[(8*j)*HP + hp];
        }
    }
}

// ---------------- bconst partials ---------------------------------------
__global__ void k_bcpart(const float* __restrict__ W_o) {
    int h = blockIdx.x;           // 0..7
    int n = threadIdx.x;          // 0..255
    float acc = 0.f;
    const float* base = W_o + (size_t)(h*256 + 128)*LAT + n;
    #pragma unroll 8
    for (int c = 0; c < DD; c++)
        acc += base[(size_t)c*LAT];
    g_bcp[h*LAT + n] = acc;
}

// ---------------- W2/W3 fp16 prep (smem-tiled transpose) ----------------
__global__ void k_prepW(const float* __restrict__ W2,
                        const float* __restrict__ W3) {
    __shared__ float s_tile[64][65];
    int bid = blockIdx.x;         // 0..79
    int tid = threadIdx.x;
    int c = tid & 63, rloc = tid >> 6;

    const float* src;
    int tk, tn, src_cols;
    bool isW2 = (bid < 64);
    if (isW2) { tk = bid >> 3; tn = bid & 7; src = W2; src_cols = 512; }
    else      { int l = bid - 64; tk = l >> 1; tn = l & 1; src = W3; src_cols = 128; }

    #pragma unroll
    for (int i = 0; i < 16; i++) {
        int row = rloc + i*4;
        s_tile[row][c] = src[(size_t)(tk*64 + row)*src_cols + tn*64 + c];
    }
    __syncthreads();
    #pragma unroll
    for (int i = 0; i < 16; i++) {
        int n = rloc + i*4;
        __half h = __float2half_rn(s_tile[c][n]);
        if (isW2) g_B2[(size_t)(tn*64 + n)*512 + tk*64 + c] = h;
        else      g_B3[(size_t)(tn*64 + n)*512 + tk*64 + c] = h;
    }
}

// ---------------- K2: scores (poly sin, no atomics) ---------------------
__global__ void k_scores(const float* __restrict__ timesteps) {
    __shared__ float s_Asin[NSIN*HP];
    __shared__ float s_lin[HP], s_off[HP];
    __shared__ float s_ws[NSIN], s_bs[NSIN];
    int tid = threadIdx.x;
    int g = blockIdx.x * 256 + tid;
    for (int i = tid; i < NSIN*HP; i += 256) s_Asin[i] = g_Asin[i];
    if (tid < HP) { s_lin[tid] = g_lin[tid]; s_off[tid] = g_off[tid]; }
    if (tid < NSIN) { s_ws[tid] = g_ws[tid]; s_bs[tid] = g_bs[tid]; }
    __syncthreads();

    float t = timesteps[g];
    float acc[HP];
    #pragma unroll
    for (int hp = 0; hp < HP; hp++) acc[hp] = fmaf(t, s_lin[hp], s_off[hp]);
    for (int j = 0; j < NSIN; j++) {
        float s = sin_poly(fmaf(t, s_ws[j], s_bs[j]));
        #pragma unroll
        for (int hp = 0; hp < HP; hp++)
            acc[hp] = fmaf(s, s_Asin[j*HP + hp], acc[hp]);
    }
    #pragma unroll
    for (int hp = 0; hp < HP; hp++)
        g_scores[g*HP + hp] = acc[hp];
}

// ---------------- K3: attention partial sums ----------------------------
__global__ void k_att_partial(const float* __restrict__ X,
                              const float* __restrict__ M) {
    __shared__ float s_m[HP];
    __shared__ __align__(16) float s_w[64*HP];
    int tid = threadIdx.x;
    int b  = blockIdx.x / SPL;
    int sp = blockIdx.x % SPL;
    int l0 = sp * LSP;
    if (tid < HP) s_m[tid] = g_bound[tid];
    float acc[HP];
    #pragma unroll
    for (int hp = 0; hp < HP; hp++) acc[hp] = 0.f;
    int c = tid;

    for (int ch = 0; ch < LSP; ch += 64) {
        __syncthreads();
        for (int i = tid; i < 64*HP; i += 256) {
            int li = i / HP, hp = i % HP;
            float sc = g_scores[(b*LL + l0 + ch + li)*HP + hp];
            s_w[i] = __expf(sc - s_m[hp]);
        }
        __syncthreads();
        for (int li = 0; li < 64; li++) {
            int l = l0 + ch + li;
            float f;
            if (c < DD) {
                float xv = X[((long)b*LL + l)*DD + c];
                float mv = M[((long)b*LL + l)*DD + c];
                f = xv * mv;
            } else {
                f = M[((long)b*LL + l)*DD + (c - DD)];
            }
            const float4* w4 = reinterpret_cast<const float4*>(&s_w[li*HP]);
            float4 w0 = w4[0], w1 = w4[1], w2 = w4[2];
            float4 w3 = w4[3], w4v = w4[4], w5 = w4[5];
            acc[0]  = fmaf(w0.x,  f, acc[0]);  acc[1]  = fmaf(w0.y,  f, acc[1]);
            acc[2]  = fmaf(w0.z,  f, acc[2]);  acc[3]  = fmaf(w0.w,  f, acc[3]);
            acc[4]  = fmaf(w1.x,  f, acc[4]);  acc[5]  = fmaf(w1.y,  f, acc[5]);
            acc[6]  = fmaf(w1.z,  f, acc[6]);  acc[7]  = fmaf(w1.w,  f, acc[7]);
            acc[8]  = fmaf(w2.x,  f, acc[8]);  acc[9]  = fmaf(w2.y,  f, acc[9]);
            acc[10] = fmaf(w2.z,  f, acc[10]); acc[11] = fmaf(w2.w,  f, acc[11]);
            acc[12] = fmaf(w3.x,  f, acc[12]); acc[13] = fmaf(w3.y,  f, acc[13]);
            acc[14] = fmaf(w3.z,  f, acc[14]); acc[15] = fmaf(w3.w,  f, acc[15]);
            acc[16] = fmaf(w4v.x, f, acc[16]); acc[17] = fmaf(w4v.y, f, acc[17]);
            acc[18] = fmaf(w4v.z, f, acc[18]); acc[19] = fmaf(w4v.w, f, acc[19]);
            acc[20] = fmaf(w5.x,  f, acc[20]); acc[21] = fmaf(w5.y,  f, acc[21]);
            acc[22] = fmaf(w5.z,  f, acc[22]); acc[23] = fmaf(w5.w,  f, acc[23]);
        }
    }
    for (int hp = 0; hp < HP; hp++)
        g_part[(((sp*BB) + b)*HP + hp)*256 + c] = acc[hp];
}

// ---------------- K5: x1 (fused reduce), coeffs, D-matrices -------------
__global__ void k_coeffs(const float* __restrict__ W_o,
                         const float* __restrict__ W1,
                         const float* __restrict__ b1,
                         const float* __restrict__ b_o) {
    __shared__ float s_x1[HP*DD];
    __shared__ float s_cf[PP*LAT];
    int tid = threadIdx.x;
    int b = blockIdx.x;
    for (int i = tid; i < HP*DD; i += 256) {
        int hp = i / DD, c = i % DD;
        float num = 0.f, den = 0.f;
        #pragma unroll
        for (int sp = 0; sp < SPL; sp++) {
            int base = (((sp*BB) + b)*HP + hp)*256;
            num += g_part[base + c];
            den += g_part[base + 128 + c];
        }
        s_x1[i] = num / den;
    }
    __syncthreads();
    {
        int n = tid;
        float bc = b_o[n];
        #pragma unroll
        for (int j = 0; j < 8; j++) bc += g_bcp[j*LAT + n];
        float a0 = bc, a1 = bc, a2 = bc;
        for (int h = 0; h < HH; h++) {
            #pragma unroll 4
            for (int c = 0; c < DD; c++) {
                float wv = W_o[(h*256 + c)*LAT + n];
                a0 = fmaf(s_x1[(h*PP + 0)*DD + c], wv, a0);
                a1 = fmaf(s_x1[(h*PP + 1)*DD + c], wv, a1);
                a2 = fmaf(s_x1[(h*PP + 2)*DD + c], wv, a2);
            }
        }
        s_cf[0*LAT + n] = a0; s_cf[1*LAT + n] = a1; s_cf[2*LAT + n] = a2;
    }
    __syncthreads();
    for (int idx = tid; idx < 3*HID; idx += 256) {
        int k = idx / HID, j = idx % HID;
        float acc = (k == 0) ? b1[j] : 0.f;
        #pragma unroll 4
        for (int n = 0; n < LAT; n++)
            acc = fmaf(s_cf[k*LAT + n], W1[n*HID + j], acc);
        g_Dm[(b*3 + k)*HID + j] = acc;
    }
}

// ---------------- mma compute: one K=64 chunk ---------------------------
__device__ __forceinline__ void mma_chunk64(
    float acc[2][8][4], uint32_t asb, uint32_t bsb,
    int m0w, int n0w, int lane)
{
    #pragma unroll
    for (int ks = 0; ks < 4; ks++) {
        uint32_t a[2][4];
        #pragma unroll
        for (int mi = 0; mi < 2; mi++) {
            uint32_t ad = asb + (uint32_t)(m0w + mi*16 + (lane & 15)) * ROWB
                        + (uint32_t)(ks*32 + ((lane >> 4) << 4));
            LDM_X4(a[mi], ad);
        }
        uint32_t bfr[4][4];
        #pragma unroll
        for (int nt = 0; nt < 4; nt++) {
            int rown = n0w + nt*16 + ((lane >> 4) << 3) + (lane & 7);
            uint32_t bd = bsb + (uint32_t)rown * ROWB
                        + (uint32_t)(ks*32 + (((lane >> 3) & 1) << 4));
            LDM_X4(bfr[nt], bd);
        }
        #pragma unroll
        for (int mi = 0; mi < 2; mi++)
            #pragma unroll
            for (int nj = 0; nj < 8; nj++)
                MMA16816(acc[mi][nj], a[mi],
                         bfr[nj >> 1][(nj & 1)*2], bfr[nj >> 1][(nj & 1)*2 + 1]);
    }
}

// ---------------- K6: W2 GEMM, single fp16, K=512 -----------------------
// dyn smem: 0 s_t(512) | 512 s_b2(512) | 1024 s_D(6144) |
// 7168 A bufs 2x18432 | 44032 B bufs 2x18432 | total 80896
#define SM2_DYN 80896

__global__ void __launch_bounds__(256, 2)
k_mlp2m(const float* __restrict__ yts, const float* __restrict__ b2) {
    extern __shared__ char sm[];
    float* s_t  = (float*)(sm);
    float* s_b2 = (float*)(sm + 512);
    float* s_D  = (float*)(sm + 1024);

    int tid = threadIdx.x, lane = tid & 31, wid = tid >> 5;
    int m0 = blockIdx.x * 128;
    int n0 = blockIdx.y * 128;
    int b = m0 >> 10;
    int m0w = (wid & 3) * 32;
    int n0w = (wid >> 2) * 64;

    if (tid < 128) s_t[tid] = yts[b*TT + (m0 & 1023) + tid];
    for (int i = tid; i < 3*HID; i += 256) s_D[i] = g_Dm[b*3*HID + i];
    if (tid < 128) s_b2[tid] = b2[n0 + tid];
    __syncthreads();

    uint32_t sb = smem_u32(sm);
    uint32_t as0 = sb + 7168, as1 = sb + 7168 + 18432;
    uint32_t bs0 = sb + 44032, bs1 = sb + 44032 + 18432;

    int grow = tid >> 1;
    int gkh  = (tid & 1) << 5;          // 0/32 within 64-k chunk
    float t = s_t[grow];

    float acc[2][8][4];
    #pragma unroll
    for (int mi = 0; mi < 2; mi++)
        #pragma unroll
        for (int nj = 0; nj < 8; nj++)
            #pragma unroll
            for (int q = 0; q < 4; q++) acc[mi][nj][q] = 0.f;

    // A = fp16(relu(D0 + t D1 + t^2 D2)), single term
    auto genA = [&](int kk, uint32_t asb) {
        int kloc = (kk << 6) + gkh;
        uint32_t p[16];
        #pragma unroll
        for (int j2 = 0; j2 < 16; j2++) {
            float f[2];
            #pragma unroll
            for (int q = 0; q < 2; q++) {
                int k = kloc + j2*2 + q;
                float v = fmaf(t, fmaf(t, s_D[1024 + k], s_D[512 + k]), s_D[k]);
                f[q] = fmaxf(v, 0.f);
            }
            p[j2] = pack2h(f[0], f[1]);
        }
        uint32_t d = asb + (uint32_t)grow*ROWB + (uint32_t)(gkh << 1);
        asm volatile("st.shared.v4.b32 [%0], {%1,%2,%3,%4};"
                     :: "r"(d), "r"(p[0]), "r"(p[1]), "r"(p[2]), "r"(p[3]));
        asm volatile("st.shared.v4.b32 [%0+16], {%1,%2,%3,%4};"
                     :: "r"(d), "r"(p[4]), "r"(p[5]), "r"(p[6]), "r"(p[7]));
        asm volatile("st.shared.v4.b32 [%0+32], {%1,%2,%3,%4};"
                     :: "r"(d), "r"(p[8]), "r"(p[9]), "r"(p[10]), "r"(p[11]));
        asm volatile("st.shared.v4.b32 [%0+48], {%1,%2,%3,%4};"
                     :: "r"(d), "r"(p[12]), "r"(p[13]), "r"(p[14]), "r"(p[15]));
    };
    auto loadB = [&](int kk, uint32_t bsb) {
        #pragma unroll
        for (int i = 0; i < 4; i++) {
            int u = tid + (i << 8);
            int n = u >> 3, q = u & 7;
            uint32_t d = bsb + (uint32_t)n*ROWB + (uint32_t)(q << 4);
            const char* s = (const char*)g_B2
                + ((size_t)(n0 + n)*512 + (size_t)kk*64)*2 + q*16;
            CP16(d, s);
        }
    };

    genA(0, as0); loadB(0, bs0); CP_COMMIT();
    for (int kk = 0; kk < NKC2; kk++) {
        int buf = kk & 1;
        if (kk + 1 < NKC2) {
            genA(kk + 1, buf ? as0 : as1);
            loadB(kk + 1, buf ? bs0 : bs1);
            CP_COMMIT();
            CP_WAIT(1);
        } else {
            CP_WAIT(0);
        }
        __syncthreads();
        mma_chunk64(acc, buf ? as1 : as0, buf ? bs1 : bs0, m0w, n0w, lane);
        __syncthreads();
    }

    // ---- epilogue: relu+bias -> fp16, smem-staged coalesced stores ----
    char* stg = sm + 7168;                   // reuse A-buf region
    const int PADR = 136;
    #pragma unroll
    for (int mi = 0; mi < 2; mi++) {
        #pragma unroll
        for (int nj = 0; nj < 8; nj++) {
            int cl = n0w + nj*8 + (lane & 3)*2;
            #pragma unroll
            for (int half = 0; half < 2; half++) {
                int r = m0w + mi*16 + (lane >> 2) + half*8;
                float f0 = fmaxf(acc[mi][nj][half*2 + 0] + s_b2[cl], 0.f);
                float f1 = fmaxf(acc[mi][nj][half*2 + 1] + s_b2[cl + 1], 0.f);
                *reinterpret_cast<uint32_t*>(stg + (r*PADR + cl)*2) = pack2h(f0, f1);
            }
        }
    }
    __syncthreads();
    #pragma unroll
    for (int ps = 0; ps < 8; ps++) {
        int u = ps*256 + tid;
        int row = u >> 4, ch = u & 15;
        uint4 v = *reinterpret_cast<uint4*>(stg + row*PADR*2 + ch*16);
        *reinterpret_cast<uint4*>((char*)g_H2 + ((size_t)(m0 + row)*HID + n0)*2 + ch*16) = v;
    }
}

// ---------------- K7: W3 GEMM, single fp16, K=512 -----------------------
// dyn smem: 0 s_b3(512) | 512 A bufs 2x18432 | 37376 B bufs 2x18432
// total 74240
#define SM3_DYN 74240

__global__ void __launch_bounds__(256, 2)
k_mlp3m(const float* __restrict__ b3, float* __restrict__ out) {
    extern __shared__ char sm[];
    float* s_b3 = (float*)(sm);

    int tid = threadIdx.x, lane = tid & 31, wid = tid >> 5;
    int m0 = blockIdx.x * 128;
    int m0w = (wid & 3) * 32;
    int n0w = (wid >> 2) * 64;

    if (tid < 128) s_b3[tid] = b3[tid];
    __syncthreads();

    uint32_t sb = smem_u32(sm);
    uint32_t as0 = sb + 512, as1 = sb + 512 + 18432;
    uint32_t bs0 = sb + 37376, bs1 = sb + 37376 + 18432;

    float acc[2][8][4];
    #pragma unroll
    for (int mi = 0; mi < 2; mi++)
        #pragma unroll
        for (int nj = 0; nj < 8; nj++)
            #pragma unroll
            for (int q = 0; q < 4; q++) acc[mi][nj][q] = 0.f;

    auto loadA = [&](int i, uint32_t asb) {
        int k0 = i << 6;
        #pragma unroll
        for (int q2 = 0; q2 < 4; q2++) {
            int u = tid + (q2 << 8);
            int row = u >> 3, q = u & 7;
            uint32_t d = asb + (uint32_t)row*ROWB + (uint32_t)(q << 4);
            const char* s = (const char*)g_H2 + ((size_t)(m0 + row)*HID + k0)*2 + q*16;
            CP16(d, s);
        }
    };
    auto loadB = [&](int i, uint32_t bsb) {
        int k0 = i << 6;
        #pragma unroll
        for (int q2 = 0; q2 < 4; q2++) {
            int u = tid + (q2 << 8);
            int n = u >> 3, q = u & 7;
            uint32_t d = bsb + (uint32_t)n*ROWB + (uint32_t)(q << 4);
            const char* s = (const char*)g_B3 + ((size_t)n*512 + k0)*2 + q*16;
            CP16(d, s);
        }
    };

    loadA(0, as0); loadB(0, bs0); CP_COMMIT();
    for (int i = 0; i < NKC3; i++) {
        int buf = i & 1;
        if (i + 1 < NKC3) {
            loadA(i + 1, buf ? as0 : as1);
            loadB(i + 1, buf ? bs0 : bs1);
            CP_COMMIT();
            CP_WAIT(1);
        } else {
            CP_WAIT(0);
        }
        __syncthreads();
        mma_chunk64(acc, buf ? as1 : as0, buf ? bs1 : bs0, m0w, n0w, lane);
        __syncthreads();
    }

    #pragma unroll
    for (int mi = 0; mi < 2; mi++) {
        #pragma unroll
        for (int nj = 0; nj < 8; nj++) {
            int cl = n0w + nj*8 + (lane & 3)*2;
            int rg = m0 + m0w + mi*16 + (lane >> 2);
            #pragma unroll
            for (int half = 0; half < 2; half++) {
                int r = rg + half*8;
                float2 v;
                v.x = acc[mi][nj][half*2 + 0] + s_b3[cl];
                v.y = acc[mi][nj][half*2 + 1] + s_b3[cl + 1];
                *reinterpret_cast<float2*>(&out[(size_t)r*DD + cl]) = v;
            }
        }
    }
}

// ---------------- launch -------------------------------------------------
extern "C" void kernel_launch(void* const* d_in, const int* in_sizes, int n_in,
                              void* d_out, int out_size) {
    const float* timesteps = (const float*)d_in[0];
    const float* X         = (const float*)d_in[1];
    const float* M         = (const float*)d_in[2];
    const float* yts       = (const float*)d_in[3];
    const float* w_te      = (const float*)d_in[4];
    const float* b_te      = (const float*)d_in[5];
    const float* query     = (const float*)d_in[6];
    const float* W_q       = (const float*)d_in[7];
    const float* b_q       = (const float*)d_in[8];
    const float* W_k       = (const float*)d_in[9];
    const float* b_k       = (const float*)d_in[10];
    const float* W_o       = (const float*)d_in[11];
    const float* b_o       = (const float*)d_in[12];
    const float* W1        = (const float*)d_in[13];
    const float* b1        = (const float*)d_in[14];
    const float* W2        = (const float*)d_in[15];
    const float* b2        = (const float*)d_in[16];
    const float* W3        = (const float*)d_in[17];
    const float* b3        = (const float*)d_in[18];
    float* out = (float*)d_out;

    cudaFuncSetAttribute(k_mlp2m, cudaFuncAttributeMaxDynamicSharedMemorySize, SM2_DYN);
    cudaFuncSetAttribute(k_mlp3m, cudaFuncAttributeMaxDynamicSharedMemorySize, SM3_DYN);

    k_setup_q<<<6, 256>>>(query, W_q, b_q);
    k_prepW<<<80, 256>>>(W2, W3);
    k_bcpart<<<8, 256>>>(W_o);
    k_setup_A<<<48, 256>>>(W_k);
    k_setup_misc<<<2, 256>>>(b_k, w_te, b_te);
    k_scores<<<BB*LL/256, 256>>>(timesteps);
    k_att_partial<<<SPL*BB, 256>>>(X, M);
    k_coeffs<<<BB, 256>>>(W_o, W1, b1, b_o);
    k_mlp2m<<<dim3(BB*TT/128, 4), 256, SM2_DYN>>>(yts, b2);
    k_mlp3m<<<BB*TT/128, 256, SM3_DYN>>>(b3, out);
}